// round 1
// baseline (speedup 1.0000x reference)
#include <cuda_runtime.h>
#include <cstdint>

// Problem constants
#define Bn   64
#define Cch  768
#define D2   196
#define Nn   64
#define Rr   32
#define KTOT (768 * 768)   // 589824

// Scratch (allocation-free: __device__ globals)
static __device__ float g_G[(size_t)Bn * Cch * Cch];   // 151 MB: G[b, c, c']
static __device__ float g_W[(size_t)Nn * Cch * Cch];   // 151 MB: W[n, c, c']
static __device__ float g_Z[Bn * Nn];                  // z logits

// ---------------------------------------------------------------------------
// Stage 0: zero the logit accumulator
// ---------------------------------------------------------------------------
__global__ void zero_z_kernel() {
    int i = blockIdx.x * blockDim.x + threadIdx.x;
    if (i < Bn * Nn) g_Z[i] = 0.0f;
}

// ---------------------------------------------------------------------------
// Stages 1 & 2: batched C = A * B^T, A,B row-major [768, K] per batch.
//   outSel = 0 -> write g_G (A=X[b], B=Y[b], K=196)
//   outSel = 1 -> write g_W (A=w0[n], B=w1[n], K=32)
// CTA tile 128x128, thread tile 8x8, 256 threads. Grid (6, 6, batch).
// ---------------------------------------------------------------------------
template <int KC>
__global__ void __launch_bounds__(256) gemm_nt_kernel(
    const float* __restrict__ A, const float* __restrict__ Bm,
    int K, long sA, long sB, int outSel)
{
    __shared__ float As[KC][132];   // [k][row-in-tile], padded (272B rows, 16B aligned)
    __shared__ float Bs[KC][132];

    const int tid = threadIdx.x;
    const int tx = tid & 15;        // col group
    const int ty = tid >> 4;        // row group
    const int bx = blockIdx.x, by = blockIdx.y, bz = blockIdx.z;

    const float* Ab = A + (long)bz * sA + (long)(by * 128) * K;
    const float* Bb = Bm + (long)bz * sB + (long)(bx * 128) * K;
    float* Cb = (outSel ? g_W : g_G) + (size_t)bz * Cch * Cch;

    float acc[8][8];
#pragma unroll
    for (int i = 0; i < 8; i++)
#pragma unroll
        for (int j = 0; j < 8; j++) acc[i][j] = 0.0f;

    for (int k0 = 0; k0 < K; k0 += KC) {
        // cooperative load: 128 rows x KC k's, each matrix
#pragma unroll
        for (int j = 0; j < (128 * KC) / 256; j++) {
            int i = tid + j * 256;
            int kk = i % KC;
            int r  = i / KC;
            int gk = k0 + kk;
            float av = 0.0f, bv = 0.0f;
            if (gk < K) {
                av = Ab[(long)r * K + gk];
                bv = Bb[(long)r * K + gk];
            }
            As[kk][r] = av;
            Bs[kk][r] = bv;
        }
        __syncthreads();

#pragma unroll
        for (int kk = 0; kk < KC; kk++) {
            float a[8], b[8];
            *(float4*)&a[0] = *(const float4*)&As[kk][ty * 8];
            *(float4*)&a[4] = *(const float4*)&As[kk][ty * 8 + 4];
            *(float4*)&b[0] = *(const float4*)&Bs[kk][tx * 8];
            *(float4*)&b[4] = *(const float4*)&Bs[kk][tx * 8 + 4];
#pragma unroll
            for (int i = 0; i < 8; i++)
#pragma unroll
                for (int j = 0; j < 8; j++)
                    acc[i][j] = fmaf(a[i], b[j], acc[i][j]);
        }
        __syncthreads();
    }

    const int row0 = by * 128 + ty * 8;
    const int col0 = bx * 128 + tx * 8;
#pragma unroll
    for (int i = 0; i < 8; i++) {
        *(float4*)&Cb[(size_t)(row0 + i) * Cch + col0]     = *(float4*)&acc[i][0];
        *(float4*)&Cb[(size_t)(row0 + i) * Cch + col0 + 4] = *(float4*)&acc[i][4];
    }
}

// ---------------------------------------------------------------------------
// Stage 3: z[b,n] += sum_k G[b,k] * W[n,k]   (k = flattened (c,c'), split-K)
// 576 CTAs, each owns a 1024-wide k slice; 64x64 outputs per CTA (4x4/thread),
// float4 k-vectorized smem reads; atomicAdd into g_Z.
// ---------------------------------------------------------------------------
__global__ void __launch_bounds__(256) reduce_kernel() {
    __shared__ float Gs[64][68];   // [b][k-sub], padded (272B rows, 16B aligned)
    __shared__ float Ws[64][68];   // [n][k-sub]

    const int tid = threadIdx.x;
    const int tx = tid & 15;       // n group
    const int ty = tid >> 4;       // b group
    const int kbase = blockIdx.x * 1024;

    float acc[4][4];
#pragma unroll
    for (int i = 0; i < 4; i++)
#pragma unroll
        for (int j = 0; j < 4; j++) acc[i][j] = 0.0f;

    for (int ks = 0; ks < 1024; ks += 64) {
        const int k0 = kbase + ks;
#pragma unroll
        for (int j = 0; j < 4; j++) {
            int i   = tid + j * 256;
            int row = i >> 4;
            int c4  = (i & 15) << 2;
            *(float4*)&Gs[row][c4] = *(const float4*)&g_G[(size_t)row * KTOT + k0 + c4];
            *(float4*)&Ws[row][c4] = *(const float4*)&g_W[(size_t)row * KTOT + k0 + c4];
        }
        __syncthreads();

#pragma unroll
        for (int kq = 0; kq < 16; kq++) {
            float4 ga[4], wb[4];
#pragma unroll
            for (int j = 0; j < 4; j++) {
                ga[j] = *(const float4*)&Gs[ty * 4 + j][kq * 4];
                wb[j] = *(const float4*)&Ws[tx * 4 + j][kq * 4];
            }
#pragma unroll
            for (int i = 0; i < 4; i++)
#pragma unroll
                for (int j = 0; j < 4; j++) {
                    acc[i][j] = fmaf(ga[i].x, wb[j].x, acc[i][j]);
                    acc[i][j] = fmaf(ga[i].y, wb[j].y, acc[i][j]);
                    acc[i][j] = fmaf(ga[i].z, wb[j].z, acc[i][j]);
                    acc[i][j] = fmaf(ga[i].w, wb[j].w, acc[i][j]);
                }
        }
        __syncthreads();
    }

#pragma unroll
    for (int i = 0; i < 4; i++)
#pragma unroll
        for (int j = 0; j < 4; j++)
            atomicAdd(&g_Z[(ty * 4 + i) * Nn + tx * 4 + j], acc[i][j]);
}

// ---------------------------------------------------------------------------
// Stage 4: out[b,n] = softmax_n( z[b,n]/196 + bias[n] )
// ---------------------------------------------------------------------------
__global__ void softmax_kernel(const float* __restrict__ bias, float* __restrict__ out) {
    const int b = blockIdx.x;
    const int n = threadIdx.x;
    __shared__ float red[Nn];

    float v = g_Z[b * Nn + n] * (1.0f / 196.0f) + bias[n];

    red[n] = v;
    __syncthreads();
    for (int s = 32; s > 0; s >>= 1) {
        if (n < s) red[n] = fmaxf(red[n], red[n + s]);
        __syncthreads();
    }
    float m = red[0];
    __syncthreads();

    float e = expf(v - m);
    red[n] = e;
    __syncthreads();
    for (int s = 32; s > 0; s >>= 1) {
        if (n < s) red[n] += red[n + s];
        __syncthreads();
    }
    out[b * Nn + n] = e / red[0];
}

// ---------------------------------------------------------------------------
// Launch
// ---------------------------------------------------------------------------
extern "C" void kernel_launch(void* const* d_in, const int* in_sizes, int n_in,
                              void* d_out, int out_size) {
    const float* X    = (const float*)d_in[0];  // [64, 768, 14, 14]
    const float* Y    = (const float*)d_in[1];  // [64, 768, 14, 14]
    const float* w    = (const float*)d_in[2];  // [2, 64, 768, 32]
    const float* bias = (const float*)d_in[3];  // [64]
    float* out = (float*)d_out;                 // [64, 64]

    zero_z_kernel<<<16, 256>>>();

    // Stage 1: G[b] = X[b] @ Y[b]^T, K = 196
    {
        dim3 grid(6, 6, Bn);
        gemm_nt_kernel<16><<<grid, 256>>>(X, Y, D2,
                                          (long)Cch * D2, (long)Cch * D2, 0);
    }
    // Stage 2: W[n] = w0[n] @ w1[n]^T, K = 32
    {
        const float* w0 = w;
        const float* w1 = w + (long)Nn * Cch * Rr;
        dim3 grid(6, 6, Nn);
        gemm_nt_kernel<16><<<grid, 256>>>(w0, w1, Rr,
                                          (long)Cch * Rr, (long)Cch * Rr, 1);
    }
    // Stage 3: split-K contraction into logits
    reduce_kernel<<<KTOT / 1024, 256>>>();

    // Stage 4: softmax
    softmax_kernel<<<Bn, Nn>>>(bias, out);
}

// round 4
// speedup vs baseline: 1.7954x; 1.7954x over previous
#include <cuda_runtime.h>
#include <cuda_bf16.h>
#include <cstdint>

#define KTOT (768*768)   // 589824

// bf16 hi/lo planes of G[b,c,c'] and W[n,c,c']  (75.5 MB each)
static __device__ __align__(16) __nv_bfloat16 g_Ghi[(size_t)64*KTOT];
static __device__ __align__(16) __nv_bfloat16 g_Glo[(size_t)64*KTOT];
static __device__ __align__(16) __nv_bfloat16 g_Whi[(size_t)64*KTOT];
static __device__ __align__(16) __nv_bfloat16 g_Wlo[(size_t)64*KTOT];
static __device__ float g_Zp[576*64*64];   // split-K partials (deterministic)
static __device__ float g_Z[64*64];

// ---------------------------------------------------------------------------
// helpers
// ---------------------------------------------------------------------------
__device__ __forceinline__ uint32_t smem_u32(const void* p) {
    uint32_t a;
    asm("{ .reg .u64 t; cvta.to.shared.u64 t, %1; cvt.u32.u64 %0, t; }" : "=r"(a) : "l"(p));
    return a;
}
#define SW128(o) ((o) ^ (((o) >> 3) & 0x70))

__device__ __forceinline__ void ldsm4(uint32_t* r, uint32_t addr) {
    asm volatile("ldmatrix.sync.aligned.m8n8.x4.shared.b16 {%0,%1,%2,%3}, [%4];"
                 : "=r"(r[0]), "=r"(r[1]), "=r"(r[2]), "=r"(r[3]) : "r"(addr));
}
__device__ __forceinline__ void mma16816(float* c, const uint32_t* a, uint32_t b0, uint32_t b1) {
    asm volatile("mma.sync.aligned.m16n8k16.row.col.f32.bf16.bf16.f32 "
                 "{%0,%1,%2,%3}, {%4,%5,%6,%7}, {%8,%9}, {%0,%1,%2,%3};"
                 : "+f"(c[0]), "+f"(c[1]), "+f"(c[2]), "+f"(c[3])
                 : "r"(a[0]), "r"(a[1]), "r"(a[2]), "r"(a[3]), "r"(b0), "r"(b1));
}

// 128x128 warp-MMA over one [128 rows][64 bf16] SW128 tile pair.
// Warp layout: wm = wid&3 -> m offset 32*wm; wn = wid>>2 -> n offset 64*wn.
__device__ __forceinline__ void compute_chunk(
    float acc[2][8][4], uint32_t aBase, uint32_t bBase, int wm, int wn, int lane)
{
    const int lrow = lane & 15, lseg = lane >> 4;
#pragma unroll
    for (int ks = 0; ks < 4; ks++) {
        uint32_t afr[2][4];
#pragma unroll
        for (int mi = 0; mi < 2; mi++) {
            int row = wm * 32 + mi * 16 + lrow;
            ldsm4(afr[mi], aBase + SW128((uint32_t)(row * 128 + ks * 32 + lseg * 16)));
        }
#pragma unroll
        for (int nj = 0; nj < 4; nj++) {
            uint32_t bfr[4];
            int row = wn * 64 + nj * 16 + lrow;
            ldsm4(bfr, bBase + SW128((uint32_t)(row * 128 + ks * 32 + lseg * 16)));
#pragma unroll
            for (int mi = 0; mi < 2; mi++) {
                mma16816(acc[mi][nj * 2],     afr[mi], bfr[0], bfr[2]);
                mma16816(acc[mi][nj * 2 + 1], afr[mi], bfr[1], bfr[3]);
            }
        }
    }
}

// Dump warp fragments into smem f32 [128][132]
__device__ __forceinline__ void dump_acc(
    float* S, const float acc[2][8][4], int wm, int wn, int lane)
{
#pragma unroll
    for (int mi = 0; mi < 2; mi++)
#pragma unroll
        for (int ni = 0; ni < 8; ni++) {
            int r = wm * 32 + mi * 16 + (lane >> 2);
            int c = wn * 64 + ni * 8 + (lane & 3) * 2;
            S[r * 132 + c]           = acc[mi][ni][0];
            S[r * 132 + c + 1]       = acc[mi][ni][1];
            S[(r + 8) * 132 + c]     = acc[mi][ni][2];
            S[(r + 8) * 132 + c + 1] = acc[mi][ni][3];
        }
}

// ---------------------------------------------------------------------------
// Stages 1 & 2: O[bz] = A[bz] @ B[bz]^T (768x768 out), K fp32 values.
// Chunk = 64 fp32 -> separate hi/lo tiles; 3 MMA passes (hihi, hilo, lohi).
// dyn smem: max(4*16384 tiles, 128*132*4 epilogue) = 67584.
// ---------------------------------------------------------------------------
__global__ void __launch_bounds__(256) gemm_kernel(
    const float* __restrict__ A, const float* __restrict__ Bm,
    int K, int nChunks, long sA, long sB, int outSel)
{
    extern __shared__ char dsm[];
    char* tAhi = dsm;
    char* tAlo = dsm + 16384;
    char* tBhi = dsm + 32768;
    char* tBlo = dsm + 49152;
    const uint32_t aHi = smem_u32(tAhi), aLo = smem_u32(tAlo);
    const uint32_t bHi = smem_u32(tBhi), bLo = smem_u32(tBlo);

    const int tid = threadIdx.x, lane = tid & 31, wid = tid >> 5;
    const int wm = wid & 3, wn = wid >> 2;
    const int bx = blockIdx.x, by = blockIdx.y, bz = blockIdx.z;

    const float* Ab = A + (long)bz * sA + (long)(by * 128) * K;
    const float* Bb = Bm + (long)bz * sB + (long)(bx * 128) * K;

    float acc[2][8][4];
#pragma unroll
    for (int i = 0; i < 2; i++)
#pragma unroll
        for (int j = 0; j < 8; j++)
#pragma unroll
            for (int q = 0; q < 4; q++) acc[i][j][q] = 0.0f;

    for (int ch = 0; ch < nChunks; ch++) {
        const int k0 = ch * 64;
        // load 128 rows x 64 fp32 per matrix; split -> hi tile + lo tile
#pragma unroll
        for (int it = 0; it < 8; it++) {
            int t   = tid + it * 256;     // 0..2047
            int m   = t >> 10;            // 0=A, 1=B
            int rem = t & 1023;
            int row = rem >> 3;           // 0..127
            int kg  = rem & 7;            // 0..7
            int gk  = k0 + kg * 8;
            const float* src = (m ? Bb : Ab) + (long)row * K + gk;
            float v[8];
            if (gk + 8 <= K) {
                float4 p0 = *(const float4*)src;
                float4 p1 = *(const float4*)(src + 4);
                v[0]=p0.x; v[1]=p0.y; v[2]=p0.z; v[3]=p0.w;
                v[4]=p1.x; v[5]=p1.y; v[6]=p1.z; v[7]=p1.w;
            } else {
#pragma unroll
                for (int j = 0; j < 8; j++) v[j] = (gk + j < K) ? src[j] : 0.0f;
            }
            union { __nv_bfloat16 h[8]; uint4 u; } hp, lp;
#pragma unroll
            for (int j = 0; j < 8; j++) {
                __nv_bfloat16 h = __float2bfloat16(v[j]);
                hp.h[j] = h;
                lp.h[j] = __float2bfloat16(v[j] - __bfloat162float(h));
            }
            uint32_t sw = SW128((uint32_t)(row * 128 + kg * 16));
            *(uint4*)((m ? tBhi : tAhi) + sw) = hp.u;
            *(uint4*)((m ? tBlo : tAlo) + sw) = lp.u;
        }
        __syncthreads();
        compute_chunk(acc, aHi, bHi, wm, wn, lane);   // hi * hi
        compute_chunk(acc, aHi, bLo, wm, wn, lane);   // hi * lo
        compute_chunk(acc, aLo, bHi, wm, wn, lane);   // lo * hi
        __syncthreads();
    }

    // epilogue: frags -> smem f32 -> bf16 hi/lo planes (coalesced)
    float* S = (float*)dsm;
    dump_acc(S, acc, wm, wn, lane);
    __syncthreads();

    __nv_bfloat16* Ohi = outSel ? g_Whi : g_Ghi;
    __nv_bfloat16* Olo = outSel ? g_Wlo : g_Glo;
#pragma unroll
    for (int it = 0; it < 32; it++) {
        int i   = tid + it * 256;      // 8192 = 128 rows x 64 bf162-cols
        int row = i >> 6;
        int c2  = i & 63;
        float2 v = *(const float2*)&S[row * 132 + c2 * 2];
        __nv_bfloat162 h2, l2;
        h2.x = __float2bfloat16(v.x);
        h2.y = __float2bfloat16(v.y);
        l2.x = __float2bfloat16(v.x - __bfloat162float(h2.x));
        l2.y = __float2bfloat16(v.y - __bfloat162float(h2.y));
        size_t g = (size_t)bz * KTOT + (size_t)(by * 128 + row) * 768 + (bx * 128 + c2 * 2);
        *(uint32_t*)&Ohi[g] = *(uint32_t*)&h2;
        *(uint32_t*)&Olo[g] = *(uint32_t*)&l2;
    }
}

// ---------------------------------------------------------------------------
// Stage 3: split-K contraction. A=[Ghi;Glo] (128 rows), B=[Whi;Wlo].
// z = sum of all 4 quadrants of the 128x128 MMA output (exact in represented
// values). 576 CTAs x 1024-k slices, 16 chunks of 64 bf16. dyn smem 67584.
// ---------------------------------------------------------------------------
__global__ void __launch_bounds__(256) contract_kernel()
{
    extern __shared__ char dsm[];
    char* tA = dsm;
    char* tB = dsm + 16384;
    const uint32_t aBase = smem_u32(tA), bBase = smem_u32(tB);

    const int tid = threadIdx.x, lane = tid & 31, wid = tid >> 5;
    const int wm = wid & 3, wn = wid >> 2;

    float acc[2][8][4];
#pragma unroll
    for (int i = 0; i < 2; i++)
#pragma unroll
        for (int j = 0; j < 8; j++)
#pragma unroll
            for (int q = 0; q < 4; q++) acc[i][j][q] = 0.0f;

    for (int ch = 0; ch < 16; ch++) {
        const long k0 = (long)blockIdx.x * 1024 + ch * 64;
#pragma unroll
        for (int it = 0; it < 8; it++) {
            int t   = tid + it * 256;
            int m   = t >> 10;          // 0 = G(A), 1 = W(B)
            int rem = t & 1023;
            int row = rem >> 3;         // 0-63 hi plane, 64-127 lo plane
            int kg  = rem & 7;
            const __nv_bfloat16* pl =
                m ? (row < 64 ? g_Whi : g_Wlo) : (row < 64 ? g_Ghi : g_Glo);
            uint4 v = *(const uint4*)(pl + (size_t)(row & 63) * KTOT + k0 + kg * 8);
            *(uint4*)((m ? tB : tA) + SW128((uint32_t)(row * 128 + kg * 16))) = v;
        }
        __syncthreads();
        compute_chunk(acc, aBase, bBase, wm, wn, lane);
        __syncthreads();
    }

    float* S = (float*)dsm;
    dump_acc(S, acc, wm, wn, lane);
    __syncthreads();

#pragma unroll
    for (int it = 0; it < 16; it++) {
        int i = tid + it * 256;        // 4096
        int b = i >> 6;
        int n = i & 63;
        float z = S[b * 132 + n] + S[b * 132 + n + 64]
                + S[(b + 64) * 132 + n] + S[(b + 64) * 132 + n + 64];
        g_Zp[(size_t)blockIdx.x * 4096 + i] = z;
    }
}

// ---------------------------------------------------------------------------
// Stage 3b: deterministic partial reduction
// ---------------------------------------------------------------------------
__global__ void reduce_z_kernel() {
    int i = blockIdx.x * 256 + threadIdx.x;
    float s = 0.0f;
#pragma unroll 8
    for (int j = 0; j < 576; j++) s += g_Zp[(size_t)j * 4096 + i];
    g_Z[i] = s;
}

// ---------------------------------------------------------------------------
// Stage 4: softmax over n of z/196 + bias
// ---------------------------------------------------------------------------
__global__ void softmax_kernel(const float* __restrict__ bias, float* __restrict__ out) {
    const int b = blockIdx.x, n = threadIdx.x;
    __shared__ float red[64];
    float v = g_Z[b * 64 + n] * (1.0f / 196.0f) + bias[n];
    red[n] = v;
    __syncthreads();
    for (int s = 32; s > 0; s >>= 1) { if (n < s) red[n] = fmaxf(red[n], red[n + s]); __syncthreads(); }
    float m = red[0];
    __syncthreads();
    float e = expf(v - m);
    red[n] = e;
    __syncthreads();
    for (int s = 32; s > 0; s >>= 1) { if (n < s) red[n] += red[n + s]; __syncthreads(); }
    out[b * 64 + n] = e / red[0];
}

// ---------------------------------------------------------------------------
// Launch
// ---------------------------------------------------------------------------
extern "C" void kernel_launch(void* const* d_in, const int* in_sizes, int n_in,
                              void* d_out, int out_size) {
    const float* X    = (const float*)d_in[0];  // [64, 768, 14, 14]
    const float* Y    = (const float*)d_in[1];  // [64, 768, 14, 14]
    const float* w    = (const float*)d_in[2];  // [2, 64, 768, 32]
    const float* bias = (const float*)d_in[3];  // [64]
    float* out = (float*)d_out;                 // [64, 64]

    // Idempotent, not a stream op — safe under graph capture; no static guards.
    cudaFuncSetAttribute(gemm_kernel,     cudaFuncAttributeMaxDynamicSharedMemorySize, 67584);
    cudaFuncSetAttribute(contract_kernel, cudaFuncAttributeMaxDynamicSharedMemorySize, 67584);

    // Stage 1: G[b] = X[b] @ Y[b]^T   (K = 196 -> 4 chunks of 64)
    {
        dim3 grid(6, 6, 64);
        gemm_kernel<<<grid, 256, 67584>>>(X, Y, 196, 4,
                                          (long)768 * 196, (long)768 * 196, 0);
    }
    // Stage 2: W[n] = w0[n] @ w1[n]^T (K = 32 -> 1 chunk)
    {
        const float* w0 = w;
        const float* w1 = w + (long)64 * 768 * 32;
        dim3 grid(6, 6, 64);
        gemm_kernel<<<grid, 256, 67584>>>(w0, w1, 32, 1,
                                          (long)768 * 32, (long)768 * 32, 1);
    }
    // Stage 3: split-K contraction + deterministic reduce
    contract_kernel<<<576, 256, 67584>>>();
    reduce_z_kernel<<<16, 256>>>();

    // Stage 4: softmax
    softmax_kernel<<<64, 64>>>(bias, out);
}

// round 5
// speedup vs baseline: 4.6423x; 2.5856x over previous
#include <cuda_runtime.h>
#include <cuda_bf16.h>
#include <cuda_fp16.h>
#include <cstdint>

#define KTOT (768*768)   // 589824

// fp16 padded input planes
static __device__ __align__(16) __half g_Xh[(size_t)64*768*256];   // 25.2 MB
static __device__ __align__(16) __half g_Yh[(size_t)64*768*256];
static __device__ __align__(16) __half g_w0h[(size_t)64*768*64];   // 6.3 MB
static __device__ __align__(16) __half g_w1h[(size_t)64*768*64];
// bf16 hi/lo planes of G[b,c,c'] and W[n,c,c']  (75.5 MB each)
static __device__ __align__(16) __nv_bfloat16 g_Ghi[(size_t)64*KTOT];
static __device__ __align__(16) __nv_bfloat16 g_Glo[(size_t)64*KTOT];
static __device__ __align__(16) __nv_bfloat16 g_Whi[(size_t)64*KTOT];
static __device__ __align__(16) __nv_bfloat16 g_Wlo[(size_t)64*KTOT];
static __device__ float g_Zp[288*64*64];   // split-K partials (deterministic)
static __device__ float g_Z[64*64];

// ---------------------------------------------------------------------------
// helpers
// ---------------------------------------------------------------------------
__device__ __forceinline__ uint32_t smem_u32(const void* p) {
    uint32_t a;
    asm("{ .reg .u64 t; cvta.to.shared.u64 t, %1; cvt.u32.u64 %0, t; }" : "=r"(a) : "l"(p));
    return a;
}
#define SW128(o) ((o) ^ (((o) >> 3) & 0x70))

__device__ __forceinline__ void cpasync16(uint32_t dst, const void* src) {
    asm volatile("cp.async.cg.shared.global [%0], [%1], 16;" :: "r"(dst), "l"(src));
}
#define CP_COMMIT() asm volatile("cp.async.commit_group;" ::: "memory")
#define CP_WAIT(n)  asm volatile("cp.async.wait_group %0;" :: "n"(n) : "memory")

__device__ __forceinline__ void ldsm4(uint32_t* r, uint32_t addr) {
    asm volatile("ldmatrix.sync.aligned.m8n8.x4.shared.b16 {%0,%1,%2,%3}, [%4];"
                 : "=r"(r[0]), "=r"(r[1]), "=r"(r[2]), "=r"(r[3]) : "r"(addr));
}
__device__ __forceinline__ void mma_fp16(float* c, const uint32_t* a, uint32_t b0, uint32_t b1) {
    asm volatile("mma.sync.aligned.m16n8k16.row.col.f32.f16.f16.f32 "
                 "{%0,%1,%2,%3}, {%4,%5,%6,%7}, {%8,%9}, {%0,%1,%2,%3};"
                 : "+f"(c[0]), "+f"(c[1]), "+f"(c[2]), "+f"(c[3])
                 : "r"(a[0]), "r"(a[1]), "r"(a[2]), "r"(a[3]), "r"(b0), "r"(b1));
}
__device__ __forceinline__ void mma_bf16(float* c, const uint32_t* a, uint32_t b0, uint32_t b1) {
    asm volatile("mma.sync.aligned.m16n8k16.row.col.f32.bf16.bf16.f32 "
                 "{%0,%1,%2,%3}, {%4,%5,%6,%7}, {%8,%9}, {%0,%1,%2,%3};"
                 : "+f"(c[0]), "+f"(c[1]), "+f"(c[2]), "+f"(c[3])
                 : "r"(a[0]), "r"(a[1]), "r"(a[2]), "r"(a[3]), "r"(b0), "r"(b1));
}

// 128x128 warp-MMA over [128 rows][64 b16] SW128 tiles; nks k-steps of 16.
// Warp layout: wm = wid&3 -> m offset 32*wm; wn = wid>>2 -> n offset 64*wn.
template <bool FP16>
__device__ __forceinline__ void compute_chunk(
    float acc[2][8][4], uint32_t aBase, uint32_t bBase, int wm, int wn, int lane, int nks)
{
    const int lrow = lane & 15, lseg = lane >> 4;
#pragma unroll
    for (int ks = 0; ks < 4; ks++) {
        if (ks >= nks) break;
        uint32_t afr[2][4];
#pragma unroll
        for (int mi = 0; mi < 2; mi++) {
            int row = wm * 32 + mi * 16 + lrow;
            ldsm4(afr[mi], aBase + SW128((uint32_t)(row * 128 + ks * 32 + lseg * 16)));
        }
#pragma unroll
        for (int nj = 0; nj < 4; nj++) {
            uint32_t bfr[4];
            int row = wn * 64 + nj * 16 + lrow;
            ldsm4(bfr, bBase + SW128((uint32_t)(row * 128 + ks * 32 + lseg * 16)));
#pragma unroll
            for (int mi = 0; mi < 2; mi++) {
                if (FP16) {
                    mma_fp16(acc[mi][nj * 2],     afr[mi], bfr[0], bfr[2]);
                    mma_fp16(acc[mi][nj * 2 + 1], afr[mi], bfr[1], bfr[3]);
                } else {
                    mma_bf16(acc[mi][nj * 2],     afr[mi], bfr[0], bfr[2]);
                    mma_bf16(acc[mi][nj * 2 + 1], afr[mi], bfr[1], bfr[3]);
                }
            }
        }
    }
}

// Dump warp fragments into smem f32 [128][132]
__device__ __forceinline__ void dump_acc(
    float* S, const float acc[2][8][4], int wm, int wn, int lane)
{
#pragma unroll
    for (int mi = 0; mi < 2; mi++)
#pragma unroll
        for (int ni = 0; ni < 8; ni++) {
            int r = wm * 32 + mi * 16 + (lane >> 2);
            int c = wn * 64 + ni * 8 + (lane & 3) * 2;
            S[r * 132 + c]           = acc[mi][ni][0];
            S[r * 132 + c + 1]       = acc[mi][ni][1];
            S[(r + 8) * 132 + c]     = acc[mi][ni][2];
            S[(r + 8) * 132 + c + 1] = acc[mi][ni][3];
        }
}

// ---------------------------------------------------------------------------
// Prep: fp32 inputs -> fp16 planes with K padding (196->256, 32->64).
// One uint4 (8 halves) per thread-slot. grid 15360 x 256.
// ---------------------------------------------------------------------------
__global__ void prep_kernel(const float* __restrict__ X, const float* __restrict__ Y,
                            const float* __restrict__ w)
{
    const long n1 = (long)64 * 768 * 32;   // uint4 slots per X/Y plane
    const long n3 = (long)64 * 768 * 8;    // uint4 slots per w plane
    long s = (long)blockIdx.x * 256 + threadIdx.x;
    union { __half h[8]; uint4 u; } o;
    if (s < 2 * n1) {
        const float* src = (s < n1) ? X : Y;
        __half* dst = (s < n1) ? g_Xh : g_Yh;
        long t = (s < n1) ? s : s - n1;
        long row = t >> 5;
        int k0 = (int)(t & 31) << 3;
#pragma unroll
        for (int j = 0; j < 8; j++) {
            int k = k0 + j;
            o.h[j] = (k < 196) ? __float2half(src[row * 196 + k]) : __half(0.0f);
        }
        *(uint4*)&dst[row * 256 + k0] = o.u;
    } else {
        long t = s - 2 * n1;
        const float* src = (t < n3) ? w : (w + (long)64 * 768 * 32);
        __half* dst = (t < n3) ? g_w0h : g_w1h;
        long u2 = (t < n3) ? t : t - n3;
        long row = u2 >> 3;
        int k0 = (int)(u2 & 7) << 3;
#pragma unroll
        for (int j = 0; j < 8; j++) {
            int k = k0 + j;
            o.h[j] = (k < 32) ? __float2half(src[row * 32 + k]) : __half(0.0f);
        }
        *(uint4*)&dst[row * 64 + k0] = o.u;
    }
}

// ---------------------------------------------------------------------------
// Unified Gram GEMM: grid (6,6,128).
//   bz <  64: G[bz] = Xh[bz] @ Yh[bz]^T  (ldk=256, 4 chunks, ksteps {4,4,4,1})
//   bz >= 64: W[n]  = w0h[n] @ w1h[n]^T  (ldk=64, 1 chunk, ksteps {2})
// Single-pass fp16 MMA. cp.async double-buffered. dyn smem 67584.
// ---------------------------------------------------------------------------
__global__ void __launch_bounds__(256) gemm_unified()
{
    extern __shared__ char dsm[];
    const int tid = threadIdx.x, lane = tid & 31, wid = tid >> 5;
    const int wm = wid & 3, wn = wid >> 2;
    const int bx = blockIdx.x, by = blockIdx.y, bz = blockIdx.z;
    const bool isW = bz >= 64;

    const __half* Ap;
    const __half* Bp;
    int ldk, nCh;
    if (isW) {
        const int n = bz - 64;
        Ap = g_w0h + (size_t)n * 768 * 64;
        Bp = g_w1h + (size_t)n * 768 * 64;
        ldk = 64; nCh = 1;
    } else {
        Ap = g_Xh + (size_t)bz * 768 * 256;
        Bp = g_Yh + (size_t)bz * 768 * 256;
        ldk = 256; nCh = 4;
    }
    const __half* Ab = Ap + (size_t)(by * 128) * ldk;
    const __half* Bb = Bp + (size_t)(bx * 128) * ldk;

    uint32_t tBase[2][2];   // [buf][A/B]
    tBase[0][0] = smem_u32(dsm);
    tBase[0][1] = tBase[0][0] + 16384;
    tBase[1][0] = tBase[0][0] + 32768;
    tBase[1][1] = tBase[0][0] + 49152;

    // issue all cp.async for one chunk into buffer q
    auto issue = [&](int ch, int q) {
#pragma unroll
        for (int it = 0; it < 8; it++) {
            int t   = tid + it * 256;     // 0..2047
            int m   = t >> 10;            // 0=A, 1=B
            int rem = t & 1023;
            int row = rem >> 3;
            int kg  = rem & 7;
            const __half* src = (m ? Bb : Ab) + (size_t)row * ldk + ch * 64 + kg * 8;
            cpasync16(tBase[q][m] + SW128((uint32_t)(row * 128 + kg * 16)), src);
        }
    };

    float acc[2][8][4];
#pragma unroll
    for (int i = 0; i < 2; i++)
#pragma unroll
        for (int j = 0; j < 8; j++)
#pragma unroll
            for (int q = 0; q < 4; q++) acc[i][j][q] = 0.0f;

    issue(0, 0);
    CP_COMMIT();
    for (int ch = 0; ch < nCh; ch++) {
        if (ch + 1 < nCh) {
            issue(ch + 1, (ch + 1) & 1);
            CP_COMMIT();
            CP_WAIT(1);
        } else {
            CP_WAIT(0);
        }
        __syncthreads();
        int nks = isW ? 2 : (ch < 3 ? 4 : 1);
        compute_chunk<true>(acc, tBase[ch & 1][0], tBase[ch & 1][1], wm, wn, lane, nks);
        __syncthreads();
    }

    // epilogue: frags -> smem f32 -> bf16 hi/lo planes (coalesced)
    float* S = (float*)dsm;
    dump_acc(S, acc, wm, wn, lane);
    __syncthreads();

    __nv_bfloat16* Ohi = (isW ? g_Whi : g_Ghi) + (size_t)(bz & 63) * KTOT;
    __nv_bfloat16* Olo = (isW ? g_Wlo : g_Glo) + (size_t)(bz & 63) * KTOT;
#pragma unroll
    for (int it = 0; it < 32; it++) {
        int i   = tid + it * 256;      // 8192 = 128 rows x 64 bf162-cols
        int row = i >> 6;
        int c2  = i & 63;
        float2 v = *(const float2*)&S[row * 132 + c2 * 2];
        __nv_bfloat162 h2, l2;
        h2.x = __float2bfloat16(v.x);
        h2.y = __float2bfloat16(v.y);
        l2.x = __float2bfloat16(v.x - __bfloat162float(h2.x));
        l2.y = __float2bfloat16(v.y - __bfloat162float(h2.y));
        size_t g = (size_t)(by * 128 + row) * 768 + (bx * 128 + c2 * 2);
        *(uint32_t*)&Ohi[g] = *(uint32_t*)&h2;
        *(uint32_t*)&Olo[g] = *(uint32_t*)&l2;
    }
}

// ---------------------------------------------------------------------------
// Stage 3: split-K contraction. A=[Ghi;Glo] (128 rows), B=[Whi;Wlo].
// z = sum of all 4 quadrants (captures all hi/lo cross terms exactly).
// 288 CTAs x 2048-k slices, 32 chunks of 64 bf16, cp.async double-buffered.
// ---------------------------------------------------------------------------
__global__ void __launch_bounds__(256) contract_kernel()
{
    extern __shared__ char dsm[];
    const int tid = threadIdx.x, lane = tid & 31, wid = tid >> 5;
    const int wm = wid & 3, wn = wid >> 2;

    uint32_t tBase[2][2];
    tBase[0][0] = smem_u32(dsm);
    tBase[0][1] = tBase[0][0] + 16384;
    tBase[1][0] = tBase[0][0] + 32768;
    tBase[1][1] = tBase[0][0] + 49152;

    auto issue = [&](int ch, int q) {
        const long k0 = (long)blockIdx.x * 2048 + ch * 64;
#pragma unroll
        for (int it = 0; it < 8; it++) {
            int t   = tid + it * 256;
            int m   = t >> 10;          // 0 = G(A), 1 = W(B)
            int rem = t & 1023;
            int row = rem >> 3;         // 0-63 hi plane, 64-127 lo plane
            int kg  = rem & 7;
            const __nv_bfloat16* pl =
                m ? (row < 64 ? g_Whi : g_Wlo) : (row < 64 ? g_Ghi : g_Glo);
            const __nv_bfloat16* src = pl + (size_t)(row & 63) * KTOT + k0 + kg * 8;
            cpasync16(tBase[q][m] + SW128((uint32_t)(row * 128 + kg * 16)), src);
        }
    };

    float acc[2][8][4];
#pragma unroll
    for (int i = 0; i < 2; i++)
#pragma unroll
        for (int j = 0; j < 8; j++)
#pragma unroll
            for (int q = 0; q < 4; q++) acc[i][j][q] = 0.0f;

    issue(0, 0);
    CP_COMMIT();
    for (int ch = 0; ch < 32; ch++) {
        if (ch + 1 < 32) {
            issue(ch + 1, (ch + 1) & 1);
            CP_COMMIT();
            CP_WAIT(1);
        } else {
            CP_WAIT(0);
        }
        __syncthreads();
        compute_chunk<false>(acc, tBase[ch & 1][0], tBase[ch & 1][1], wm, wn, lane, 4);
        __syncthreads();
    }

    float* S = (float*)dsm;
    dump_acc(S, acc, wm, wn, lane);
    __syncthreads();

#pragma unroll
    for (int it = 0; it < 16; it++) {
        int i = tid + it * 256;        // 4096
        int b = i >> 6;
        int n = i & 63;
        float z = S[b * 132 + n] + S[b * 132 + n + 64]
                + S[(b + 64) * 132 + n] + S[(b + 64) * 132 + n + 64];
        g_Zp[(size_t)blockIdx.x * 4096 + i] = z;
    }
}

// ---------------------------------------------------------------------------
// Stage 3b: deterministic parallel reduction of 288 partials.
// grid 256: each CTA 16 outputs, 16 threads/output, 18 j's each + smem tree.
// ---------------------------------------------------------------------------
__global__ void reduce_z_kernel() {
    __shared__ float sd[256];
    const int il = threadIdx.x & 15, jt = threadIdx.x >> 4;
    const int i = blockIdx.x * 16 + il;
    float s = 0.0f;
#pragma unroll
    for (int u = 0; u < 18; u++) s += g_Zp[(size_t)(jt + u * 16) * 4096 + i];
    sd[threadIdx.x] = s;
    __syncthreads();
    for (int off = 8; off; off >>= 1) {
        if (jt < off) sd[threadIdx.x] += sd[threadIdx.x + off * 16];
        __syncthreads();
    }
    if (jt == 0) g_Z[i] = sd[il];
}

// ---------------------------------------------------------------------------
// Stage 4: softmax over n of z/196 + bias
// ---------------------------------------------------------------------------
__global__ void softmax_kernel(const float* __restrict__ bias, float* __restrict__ out) {
    const int b = blockIdx.x, n = threadIdx.x;
    __shared__ float red[64];
    float v = g_Z[b * 64 + n] * (1.0f / 196.0f) + bias[n];
    red[n] = v;
    __syncthreads();
    for (int s = 32; s > 0; s >>= 1) { if (n < s) red[n] = fmaxf(red[n], red[n + s]); __syncthreads(); }
    float m = red[0];
    __syncthreads();
    float e = expf(v - m);
    red[n] = e;
    __syncthreads();
    for (int s = 32; s > 0; s >>= 1) { if (n < s) red[n] += red[n + s]; __syncthreads(); }
    out[b * 64 + n] = e / red[0];
}

// ---------------------------------------------------------------------------
// Launch
// ---------------------------------------------------------------------------
extern "C" void kernel_launch(void* const* d_in, const int* in_sizes, int n_in,
                              void* d_out, int out_size) {
    const float* X    = (const float*)d_in[0];  // [64, 768, 14, 14]
    const float* Y    = (const float*)d_in[1];  // [64, 768, 14, 14]
    const float* w    = (const float*)d_in[2];  // [2, 64, 768, 32]
    const float* bias = (const float*)d_in[3];  // [64]
    float* out = (float*)d_out;                 // [64, 64]

    // Idempotent, not a stream op — safe under graph capture.
    cudaFuncSetAttribute(gemm_unified,    cudaFuncAttributeMaxDynamicSharedMemorySize, 67584);
    cudaFuncSetAttribute(contract_kernel, cudaFuncAttributeMaxDynamicSharedMemorySize, 67584);

    // Stage 0: fp32 -> fp16 padded planes
    prep_kernel<<<15360, 256>>>(X, Y, w);

    // Stages 1+2 fused: Gram of (X,Y) and of (w0,w1)
    {
        dim3 grid(6, 6, 128);
        gemm_unified<<<grid, 256, 67584>>>();
    }

    // Stage 3: split-K contraction + deterministic reduce
    contract_kernel<<<288, 256, 67584>>>();
    reduce_z_kernel<<<256, 256>>>();

    // Stage 4: softmax
    softmax_kernel<<<64, 64>>>(bias, out);
}

// round 6
// speedup vs baseline: 5.9116x; 1.2734x over previous
#include <cuda_runtime.h>
#include <cuda_bf16.h>
#include <cuda_fp16.h>
#include <cstdint>

#define KTOT (768*768)   // 589824

// fp16 padded input planes
static __device__ __align__(16) __half g_Xh[(size_t)64*768*256];   // 25.2 MB
static __device__ __align__(16) __half g_Yh[(size_t)64*768*256];
static __device__ __align__(16) __half g_w0h[(size_t)64*768*64];   // 6.3 MB
static __device__ __align__(16) __half g_w1h[(size_t)64*768*64];
// fp16 planes of G[b,c,c'] and W[n,c,c']  (75.5 MB each)
static __device__ __align__(16) __half g_Gh[(size_t)64*KTOT];
static __device__ __align__(16) __half g_Wh[(size_t)64*KTOT];
static __device__ float g_Zp[288*64*64];   // split-K partials (deterministic)

// ---------------------------------------------------------------------------
// helpers
// ---------------------------------------------------------------------------
__device__ __forceinline__ uint32_t smem_u32(const void* p) {
    uint32_t a;
    asm("{ .reg .u64 t; cvta.to.shared.u64 t, %1; cvt.u32.u64 %0, t; }" : "=r"(a) : "l"(p));
    return a;
}
#define SW128(o) ((o) ^ (((o) >> 3) & 0x70))

__device__ __forceinline__ void cpasync16(uint32_t dst, const void* src) {
    asm volatile("cp.async.cg.shared.global [%0], [%1], 16;" :: "r"(dst), "l"(src));
}
#define CP_COMMIT() asm volatile("cp.async.commit_group;" ::: "memory")
#define CP_WAIT(n)  asm volatile("cp.async.wait_group %0;" :: "n"(n) : "memory")

__device__ __forceinline__ void ldsm4(uint32_t* r, uint32_t addr) {
    asm volatile("ldmatrix.sync.aligned.m8n8.x4.shared.b16 {%0,%1,%2,%3}, [%4];"
                 : "=r"(r[0]), "=r"(r[1]), "=r"(r[2]), "=r"(r[3]) : "r"(addr));
}
__device__ __forceinline__ void mma_fp16(float* c, const uint32_t* a, uint32_t b0, uint32_t b1) {
    asm volatile("mma.sync.aligned.m16n8k16.row.col.f32.f16.f16.f32 "
                 "{%0,%1,%2,%3}, {%4,%5,%6,%7}, {%8,%9}, {%0,%1,%2,%3};"
                 : "+f"(c[0]), "+f"(c[1]), "+f"(c[2]), "+f"(c[3])
                 : "r"(a[0]), "r"(a[1]), "r"(a[2]), "r"(a[3]), "r"(b0), "r"(b1));
}

// 128x128 warp-MMA over [128 rows][64 halves] SW128 tiles; nks k-steps of 16.
// Warp layout: wm = wid&3 -> m offset 32*wm; wn = wid>>2 -> n offset 64*wn.
__device__ __forceinline__ void compute_chunk(
    float acc[2][8][4], uint32_t aBase, uint32_t bBase, int wm, int wn, int lane, int nks)
{
    const int lrow = lane & 15, lseg = lane >> 4;
#pragma unroll
    for (int ks = 0; ks < 4; ks++) {
        if (ks >= nks) break;
        uint32_t afr[2][4];
#pragma unroll
        for (int mi = 0; mi < 2; mi++) {
            int row = wm * 32 + mi * 16 + lrow;
            ldsm4(afr[mi], aBase + SW128((uint32_t)(row * 128 + ks * 32 + lseg * 16)));
        }
#pragma unroll
        for (int nj = 0; nj < 4; nj++) {
            uint32_t bfr[4];
            int row = wn * 64 + nj * 16 + lrow;
            ldsm4(bfr, bBase + SW128((uint32_t)(row * 128 + ks * 32 + lseg * 16)));
#pragma unroll
            for (int mi = 0; mi < 2; mi++) {
                mma_fp16(acc[mi][nj * 2],     afr[mi], bfr[0], bfr[2]);
                mma_fp16(acc[mi][nj * 2 + 1], afr[mi], bfr[1], bfr[3]);
            }
        }
    }
}

// ---------------------------------------------------------------------------
// Prep: fp32 inputs -> fp16 planes with K padding (196->256, 32->64).
// ---------------------------------------------------------------------------
__global__ void prep_kernel(const float* __restrict__ X, const float* __restrict__ Y,
                            const float* __restrict__ w)
{
    const long n1 = (long)64 * 768 * 32;   // uint4 slots per X/Y plane
    const long n3 = (long)64 * 768 * 8;    // uint4 slots per w plane
    long s = (long)blockIdx.x * 256 + threadIdx.x;
    union { __half h[8]; uint4 u; } o;
    if (s < 2 * n1) {
        const float* src = (s < n1) ? X : Y;
        __half* dst = (s < n1) ? g_Xh : g_Yh;
        long t = (s < n1) ? s : s - n1;
        long row = t >> 5;
        int k0 = (int)(t & 31) << 3;
#pragma unroll
        for (int j = 0; j < 8; j++) {
            int k = k0 + j;
            o.h[j] = (k < 196) ? __float2half(src[row * 196 + k]) : __half(0.0f);
        }
        *(uint4*)&dst[row * 256 + k0] = o.u;
    } else {
        long t = s - 2 * n1;
        const float* src = (t < n3) ? w : (w + (long)64 * 768 * 32);
        __half* dst = (t < n3) ? g_w0h : g_w1h;
        long u2 = (t < n3) ? t : t - n3;
        long row = u2 >> 3;
        int k0 = (int)(u2 & 7) << 3;
#pragma unroll
        for (int j = 0; j < 8; j++) {
            int k = k0 + j;
            o.h[j] = (k < 32) ? __float2half(src[row * 32 + k]) : __half(0.0f);
        }
        *(uint4*)&dst[row * 64 + k0] = o.u;
    }
}

// ---------------------------------------------------------------------------
// Unified Gram GEMM: grid (6,6,128).
//   bz <  64: G[bz] = Xh[bz] @ Yh[bz]^T  (ldk=256, 4 chunks, ksteps {4,4,4,1})
//   bz >= 64: W[n]  = w0h[n] @ w1h[n]^T  (ldk=64, 1 chunk, 2 ksteps)
// Single-pass fp16 MMA, cp.async double-buffered, fp16 output plane.
// dyn smem: max(4*16KB tiles, 128*132*4 epilogue) = 67584.
// ---------------------------------------------------------------------------
__global__ void __launch_bounds__(256) gemm_unified()
{
    extern __shared__ char dsm[];
    const int tid = threadIdx.x, lane = tid & 31, wid = tid >> 5;
    const int wm = wid & 3, wn = wid >> 2;
    const int bx = blockIdx.x, by = blockIdx.y, bz = blockIdx.z;
    const bool isW = bz >= 64;

    const __half* Ap;
    const __half* Bp;
    int ldk, nCh;
    if (isW) {
        const int n = bz - 64;
        Ap = g_w0h + (size_t)n * 768 * 64;
        Bp = g_w1h + (size_t)n * 768 * 64;
        ldk = 64; nCh = 1;
    } else {
        Ap = g_Xh + (size_t)bz * 768 * 256;
        Bp = g_Yh + (size_t)bz * 768 * 256;
        ldk = 256; nCh = 4;
    }
    const __half* Ab = Ap + (size_t)(by * 128) * ldk;
    const __half* Bb = Bp + (size_t)(bx * 128) * ldk;

    uint32_t tBase[2][2];   // [buf][A/B]
    tBase[0][0] = smem_u32(dsm);
    tBase[0][1] = tBase[0][0] + 16384;
    tBase[1][0] = tBase[0][0] + 32768;
    tBase[1][1] = tBase[0][0] + 49152;

    auto issue = [&](int ch, int q) {
#pragma unroll
        for (int it = 0; it < 8; it++) {
            int t   = tid + it * 256;     // 0..2047
            int m   = t >> 10;            // 0=A, 1=B
            int rem = t & 1023;
            int row = rem >> 3;
            int kg  = rem & 7;
            const __half* src = (m ? Bb : Ab) + (size_t)row * ldk + ch * 64 + kg * 8;
            cpasync16(tBase[q][m] + SW128((uint32_t)(row * 128 + kg * 16)), src);
        }
    };

    float acc[2][8][4];
#pragma unroll
    for (int i = 0; i < 2; i++)
#pragma unroll
        for (int j = 0; j < 8; j++)
#pragma unroll
            for (int q = 0; q < 4; q++) acc[i][j][q] = 0.0f;

    issue(0, 0);
    CP_COMMIT();
    for (int ch = 0; ch < nCh; ch++) {
        if (ch + 1 < nCh) {
            issue(ch + 1, (ch + 1) & 1);
            CP_COMMIT();
            CP_WAIT(1);
        } else {
            CP_WAIT(0);
        }
        __syncthreads();
        int nks = isW ? 2 : (ch < 3 ? 4 : 1);
        compute_chunk(acc, tBase[ch & 1][0], tBase[ch & 1][1], wm, wn, lane, nks);
        __syncthreads();
    }

    // epilogue: frags -> smem f32 -> fp16 plane (coalesced uint32 stores)
    float* S = (float*)dsm;
#pragma unroll
    for (int mi = 0; mi < 2; mi++)
#pragma unroll
        for (int ni = 0; ni < 8; ni++) {
            int r = wm * 32 + mi * 16 + (lane >> 2);
            int c = wn * 64 + ni * 8 + (lane & 3) * 2;
            S[r * 132 + c]           = acc[mi][ni][0];
            S[r * 132 + c + 1]       = acc[mi][ni][1];
            S[(r + 8) * 132 + c]     = acc[mi][ni][2];
            S[(r + 8) * 132 + c + 1] = acc[mi][ni][3];
        }
    __syncthreads();

    __half* Oh = (isW ? g_Wh : g_Gh) + (size_t)(bz & 63) * KTOT;
#pragma unroll
    for (int it = 0; it < 32; it++) {
        int i   = tid + it * 256;      // 8192 = 128 rows x 64 half2-cols
        int row = i >> 6;
        int c2  = i & 63;
        float2 v = *(const float2*)&S[row * 132 + c2 * 2];
        __half2 h2 = __floats2half2_rn(v.x, v.y);
        size_t g = (size_t)(by * 128 + row) * 768 + (bx * 128 + c2 * 2);
        *(uint32_t*)&Oh[g] = *(uint32_t*)&h2;
    }
}

// ---------------------------------------------------------------------------
// Stage 3: split-K contraction, 64x64 output per CTA.
// z_partial[b,n] = sum_k G[b,k] * W[n,k] over a 2048-k slice.
// 288 CTAs, 32 chunks of 64, cp.async double-buffered, fp16 MMA.
// Warp layout: wm = wid&3 -> 16 rows; wn = wid>>2 -> 32 cols.
// ---------------------------------------------------------------------------
__global__ void __launch_bounds__(256) contract_kernel()
{
    __shared__ __align__(128) char sm[32768];   // 2 bufs x (A 8KB + B 8KB)
    const int tid = threadIdx.x, lane = tid & 31, wid = tid >> 5;
    const int wm = wid & 3, wn = wid >> 2;
    const int lrow = lane & 15, lseg = lane >> 4;

    uint32_t tBase[2][2];
    tBase[0][0] = smem_u32(sm);
    tBase[0][1] = tBase[0][0] + 8192;
    tBase[1][0] = tBase[0][0] + 16384;
    tBase[1][1] = tBase[0][0] + 24576;

    auto issue = [&](int ch, int q) {
        const long k0 = (long)blockIdx.x * 2048 + ch * 64;
#pragma unroll
        for (int it = 0; it < 4; it++) {
            int t   = tid + it * 256;   // 0..1023
            int m   = t >> 9;           // 0 = G(A), 1 = W(B)
            int rem = t & 511;
            int row = rem >> 3;         // 0..63
            int kg  = rem & 7;
            const __half* src = (m ? g_Wh : g_Gh) + (size_t)row * KTOT + k0 + kg * 8;
            cpasync16(tBase[q][m] + SW128((uint32_t)(row * 128 + kg * 16)), src);
        }
    };

    float acc[4][4];
#pragma unroll
    for (int j = 0; j < 4; j++)
#pragma unroll
        for (int q = 0; q < 4; q++) acc[j][q] = 0.0f;

    issue(0, 0);
    CP_COMMIT();
    for (int ch = 0; ch < 32; ch++) {
        if (ch + 1 < 32) {
            issue(ch + 1, (ch + 1) & 1);
            CP_COMMIT();
            CP_WAIT(1);
        } else {
            CP_WAIT(0);
        }
        __syncthreads();
        uint32_t aBase = tBase[ch & 1][0], bBase = tBase[ch & 1][1];
#pragma unroll
        for (int ks = 0; ks < 4; ks++) {
            uint32_t afr[4];
            int arow = wm * 16 + lrow;
            ldsm4(afr, aBase + SW128((uint32_t)(arow * 128 + ks * 32 + lseg * 16)));
#pragma unroll
            for (int nj = 0; nj < 2; nj++) {
                uint32_t bfr[4];
                int brow = wn * 32 + nj * 16 + lrow;
                ldsm4(bfr, bBase + SW128((uint32_t)(brow * 128 + ks * 32 + lseg * 16)));
                mma_fp16(acc[nj * 2],     afr, bfr[0], bfr[2]);
                mma_fp16(acc[nj * 2 + 1], afr, bfr[1], bfr[3]);
            }
        }
        __syncthreads();
    }

    // write partials straight from fragments (float2, coalesced enough)
    float* outp = g_Zp + (size_t)blockIdx.x * 4096;
#pragma unroll
    for (int nj = 0; nj < 4; nj++) {
        int r = wm * 16 + (lane >> 2);
        int c = wn * 32 + nj * 8 + (lane & 3) * 2;
        *(float2*)&outp[r * 64 + c]       = make_float2(acc[nj][0], acc[nj][1]);
        *(float2*)&outp[(r + 8) * 64 + c] = make_float2(acc[nj][2], acc[nj][3]);
    }
}

// ---------------------------------------------------------------------------
// Fused reduce (288 partials) + softmax. 64 CTAs (one per b), 256 threads.
// ---------------------------------------------------------------------------
__global__ void reduce_softmax_kernel(const float* __restrict__ bias, float* __restrict__ out) {
    const int b = blockIdx.x;
    const int g = threadIdx.x >> 6, n = threadIdx.x & 63;
    __shared__ float sd[4][64];
    __shared__ float red[64];

    float s = 0.0f;
#pragma unroll 8
    for (int u = 0; u < 72; u++)
        s += g_Zp[(size_t)(g * 72 + u) * 4096 + b * 64 + n];
    sd[g][n] = s;
    __syncthreads();

    float z = 0.0f;
    if (g == 0) {
        z = (sd[0][n] + sd[1][n] + sd[2][n] + sd[3][n]) * (1.0f / 196.0f) + bias[n];
        red[n] = z;
    }
    __syncthreads();
    for (int off = 32; off > 0; off >>= 1) {
        if (g == 0 && n < off) red[n] = fmaxf(red[n], red[n + off]);
        __syncthreads();
    }
    float m = red[0];
    __syncthreads();
    float e = 0.0f;
    if (g == 0) { e = expf(z - m); red[n] = e; }
    __syncthreads();
    for (int off = 32; off > 0; off >>= 1) {
        if (g == 0 && n < off) red[n] += red[n + off];
        __syncthreads();
    }
    if (g == 0) out[b * 64 + n] = e / red[0];
}

// ---------------------------------------------------------------------------
// Launch
// ---------------------------------------------------------------------------
extern "C" void kernel_launch(void* const* d_in, const int* in_sizes, int n_in,
                              void* d_out, int out_size) {
    const float* X    = (const float*)d_in[0];  // [64, 768, 14, 14]
    const float* Y    = (const float*)d_in[1];  // [64, 768, 14, 14]
    const float* w    = (const float*)d_in[2];  // [2, 64, 768, 32]
    const float* bias = (const float*)d_in[3];  // [64]
    float* out = (float*)d_out;                 // [64, 64]

    // Idempotent, not a stream op — safe under graph capture.
    cudaFuncSetAttribute(gemm_unified, cudaFuncAttributeMaxDynamicSharedMemorySize, 67584);

    // Stage 0: fp32 -> fp16 padded planes
    prep_kernel<<<15360, 256>>>(X, Y, w);

    // Stages 1+2 fused: Gram of (X,Y) and of (w0,w1) -> fp16 planes
    {
        dim3 grid(6, 6, 128);
        gemm_unified<<<grid, 256, 67584>>>();
    }

    // Stage 3: split-K contraction
    contract_kernel<<<288, 256>>>();

    // Stage 3b+4: deterministic reduce + softmax, fused
    reduce_softmax_kernel<<<64, 256>>>(bias, out);
}

// round 7
// speedup vs baseline: 6.4790x; 1.0960x over previous
#include <cuda_runtime.h>
#include <cuda_bf16.h>
#include <cuda_fp16.h>
#include <cstdint>

#define KTOT (768*768)   // 589824
#define LDK1 208         // X/Y padded K (196 -> 208)

// fp16 padded input planes
static __device__ __align__(16) __half g_Xh[(size_t)64*768*LDK1];  // 20.4 MB
static __device__ __align__(16) __half g_Yh[(size_t)64*768*LDK1];
static __device__ __align__(16) __half g_w0h[(size_t)64*768*64];   // 6.3 MB
static __device__ __align__(16) __half g_w1h[(size_t)64*768*64];
// fp16 planes of G[b,c,c'] and W[n,c,c']  (75.5 MB each)
static __device__ __align__(16) __half g_Gh[(size_t)64*KTOT];
static __device__ __align__(16) __half g_Wh[(size_t)64*KTOT];
static __device__ float g_Zp[288*64*64];   // split-K partials (deterministic)

// ---------------------------------------------------------------------------
// helpers
// ---------------------------------------------------------------------------
__device__ __forceinline__ uint32_t smem_u32(const void* p) {
    uint32_t a;
    asm("{ .reg .u64 t; cvta.to.shared.u64 t, %1; cvt.u32.u64 %0, t; }" : "=r"(a) : "l"(p));
    return a;
}
#define SW128(o) ((o) ^ (((o) >> 3) & 0x70))

__device__ __forceinline__ void cpasync16(uint32_t dst, const void* src) {
    asm volatile("cp.async.cg.shared.global [%0], [%1], 16;" :: "r"(dst), "l"(src));
}
#define CP_COMMIT() asm volatile("cp.async.commit_group;" ::: "memory")
#define CP_WAIT(n)  asm volatile("cp.async.wait_group %0;" :: "n"(n) : "memory")

__device__ __forceinline__ void ldsm4(uint32_t* r, uint32_t addr) {
    asm volatile("ldmatrix.sync.aligned.m8n8.x4.shared.b16 {%0,%1,%2,%3}, [%4];"
                 : "=r"(r[0]), "=r"(r[1]), "=r"(r[2]), "=r"(r[3]) : "r"(addr));
}
__device__ __forceinline__ void mma_fp16(float* c, const uint32_t* a, uint32_t b0, uint32_t b1) {
    asm volatile("mma.sync.aligned.m16n8k16.row.col.f32.f16.f16.f32 "
                 "{%0,%1,%2,%3}, {%4,%5,%6,%7}, {%8,%9}, {%0,%1,%2,%3};"
                 : "+f"(c[0]), "+f"(c[1]), "+f"(c[2]), "+f"(c[3])
                 : "r"(a[0]), "r"(a[1]), "r"(a[2]), "r"(a[3]), "r"(b0), "r"(b1));
}

// 128x128 warp-MMA over [128 rows][64 halves] SW128 tiles; nks k-steps of 16.
__device__ __forceinline__ void compute_chunk(
    float acc[2][8][4], uint32_t aBase, uint32_t bBase, int wm, int wn, int lane, int nks)
{
    const int lrow = lane & 15, lseg = lane >> 4;
#pragma unroll
    for (int ks = 0; ks < 4; ks++) {
        if (ks >= nks) break;
        uint32_t afr[2][4];
#pragma unroll
        for (int mi = 0; mi < 2; mi++) {
            int row = wm * 32 + mi * 16 + lrow;
            ldsm4(afr[mi], aBase + SW128((uint32_t)(row * 128 + ks * 32 + lseg * 16)));
        }
#pragma unroll
        for (int nj = 0; nj < 4; nj++) {
            uint32_t bfr[4];
            int row = wn * 64 + nj * 16 + lrow;
            ldsm4(bfr, bBase + SW128((uint32_t)(row * 128 + ks * 32 + lseg * 16)));
#pragma unroll
            for (int mi = 0; mi < 2; mi++) {
                mma_fp16(acc[mi][nj * 2],     afr[mi], bfr[0], bfr[2]);
                mma_fp16(acc[mi][nj * 2 + 1], afr[mi], bfr[1], bfr[3]);
            }
        }
    }
}

// ---------------------------------------------------------------------------
// Prep: fp32 inputs -> fp16 planes. X/Y: 196 -> 208 cols; w: 32 -> 64 cols.
// One uint4 (8 halves) per slot. grid 13056 x 256 (exact).
// ---------------------------------------------------------------------------
__global__ void prep_kernel(const float* __restrict__ X, const float* __restrict__ Y,
                            const float* __restrict__ w)
{
    const long n1 = (long)64 * 768 * 26;   // uint4 slots per X/Y plane
    const long n3 = (long)64 * 768 * 8;    // uint4 slots per w plane
    long s = (long)blockIdx.x * 256 + threadIdx.x;
    union { __half h[8]; uint4 u; } o;
    if (s < 2 * n1) {
        const float* src = (s < n1) ? X : Y;
        __half* dst = (s < n1) ? g_Xh : g_Yh;
        long t = (s < n1) ? s : s - n1;
        long row = t / 26;
        int slot = (int)(t % 26);
        int k0 = slot * 8;
        if (slot < 23) {               // k0+8 <= 188+8 <= 196: full vector
            float4 p0 = *(const float4*)&src[row * 196 + k0];
            float4 p1 = *(const float4*)&src[row * 196 + k0 + 4];
            o.h[0] = __float2half(p0.x); o.h[1] = __float2half(p0.y);
            o.h[2] = __float2half(p0.z); o.h[3] = __float2half(p0.w);
            o.h[4] = __float2half(p1.x); o.h[5] = __float2half(p1.y);
            o.h[6] = __float2half(p1.z); o.h[7] = __float2half(p1.w);
        } else {
#pragma unroll
            for (int j = 0; j < 8; j++) {
                int k = k0 + j;
                o.h[j] = (k < 196) ? __float2half(src[row * 196 + k]) : __half(0.0f);
            }
        }
        *(uint4*)&dst[row * LDK1 + k0] = o.u;
    } else {
        long t = s - 2 * n1;
        const float* src = (t < n3) ? w : (w + (long)64 * 768 * 32);
        __half* dst = (t < n3) ? g_w0h : g_w1h;
        long u2 = (t < n3) ? t : t - n3;
        long row = u2 >> 3;
        int k0 = (int)(u2 & 7) << 3;
#pragma unroll
        for (int j = 0; j < 8; j++) {
            int k = k0 + j;
            o.h[j] = (k < 32) ? __float2half(src[row * 32 + k]) : __half(0.0f);
        }
        *(uint4*)&dst[row * 64 + k0] = o.u;
    }
}

// ---------------------------------------------------------------------------
// Unified Gram GEMM: grid (6,6,128).
//   bz <  64: G[bz] = Xh[bz] @ Yh[bz]^T  (ldk=208; chunks {64,64,64,16} cols,
//             ksteps {4,4,4,1} = 13)
//   bz >= 64: W[n]  = w0h[n] @ w1h[n]^T  (ldk=64; 1 chunk, 32 cols, 2 ksteps)
// Single-pass fp16 MMA, cp.async double-buffered, fp16-direct epilogue.
// dyn smem 65536 (4 x 16KB tiles; epilogue reuses 34816 B).
// ---------------------------------------------------------------------------
__global__ void __launch_bounds__(256) gemm_unified()
{
    extern __shared__ char dsm[];
    const int tid = threadIdx.x, lane = tid & 31, wid = tid >> 5;
    const int wm = wid & 3, wn = wid >> 2;
    const int bx = blockIdx.x, by = blockIdx.y, bz = blockIdx.z;
    const bool isW = bz >= 64;

    const __half* Ap;
    const __half* Bp;
    int ldk, nCh;
    if (isW) {
        const int n = bz - 64;
        Ap = g_w0h + (size_t)n * 768 * 64;
        Bp = g_w1h + (size_t)n * 768 * 64;
        ldk = 64; nCh = 1;
    } else {
        Ap = g_Xh + (size_t)bz * 768 * LDK1;
        Bp = g_Yh + (size_t)bz * 768 * LDK1;
        ldk = LDK1; nCh = 4;
    }
    const __half* Ab = Ap + (size_t)(by * 128) * ldk;
    const __half* Bb = Bp + (size_t)(bx * 128) * ldk;

    uint32_t tBase[2][2];   // [buf][A/B]
    tBase[0][0] = smem_u32(dsm);
    tBase[0][1] = tBase[0][0] + 16384;
    tBase[1][0] = tBase[0][0] + 32768;
    tBase[1][1] = tBase[0][0] + 49152;

    // kgmax: # of 8-half column groups actually loaded for this chunk
    auto issue = [&](int ch, int q, int kgmax) {
#pragma unroll
        for (int it = 0; it < 8; it++) {
            int t   = tid + it * 256;     // 0..2047
            int m   = t >> 10;            // 0=A, 1=B
            int rem = t & 1023;
            int row = rem >> 3;
            int kg  = rem & 7;
            if (kg < kgmax) {
                const __half* src = (m ? Bb : Ab) + (size_t)row * ldk + ch * 64 + kg * 8;
                cpasync16(tBase[q][m] + SW128((uint32_t)(row * 128 + kg * 16)), src);
            }
        }
    };

    float acc[2][8][4];
#pragma unroll
    for (int i = 0; i < 2; i++)
#pragma unroll
        for (int j = 0; j < 8; j++)
#pragma unroll
            for (int q = 0; q < 4; q++) acc[i][j][q] = 0.0f;

    issue(0, 0, isW ? 4 : 8);
    CP_COMMIT();
    for (int ch = 0; ch < nCh; ch++) {
        if (ch + 1 < nCh) {
            issue(ch + 1, (ch + 1) & 1, (ch + 1 < 3) ? 8 : 2);
            CP_COMMIT();
            CP_WAIT(1);
        } else {
            CP_WAIT(0);
        }
        __syncthreads();
        int nks = isW ? 2 : (ch < 3 ? 4 : 1);
        compute_chunk(acc, tBase[ch & 1][0], tBase[ch & 1][1], wm, wn, lane, nks);
        __syncthreads();
    }

    // epilogue: fragments -> half2 -> smem fp16 [128][68 u32 pitch] -> global
    uint32_t* Sh = (uint32_t*)dsm;
#pragma unroll
    for (int mi = 0; mi < 2; mi++)
#pragma unroll
        for (int ni = 0; ni < 8; ni++) {
            int r  = wm * 32 + mi * 16 + (lane >> 2);
            int c2 = wn * 32 + ni * 4 + (lane & 3);
            __half2 h0 = __floats2half2_rn(acc[mi][ni][0], acc[mi][ni][1]);
            __half2 h1 = __floats2half2_rn(acc[mi][ni][2], acc[mi][ni][3]);
            Sh[r * 68 + c2]       = *(uint32_t*)&h0;
            Sh[(r + 8) * 68 + c2] = *(uint32_t*)&h1;
        }
    __syncthreads();

    __half* Oh = (isW ? g_Wh : g_Gh) + (size_t)(bz & 63) * KTOT;
#pragma unroll
    for (int it = 0; it < 8; it++) {
        int idx = tid + it * 256;      // 2048 uint4 = 128 rows x 16
        int row = idx >> 4;
        int c4  = (idx & 15) * 4;      // uint32 col (pairs of halves)
        uint4 v = *(const uint4*)&Sh[row * 68 + c4];
        *(uint4*)&Oh[(size_t)(by * 128 + row) * 768 + bx * 128 + c4 * 2] = v;
    }
}

// ---------------------------------------------------------------------------
// Stage 3: split-K contraction, 64x64 output per CTA.
// 288 CTAs x 2048-k slices, 32 chunks of 64, cp.async double-buffered.
// ---------------------------------------------------------------------------
__global__ void __launch_bounds__(256) contract_kernel()
{
    __shared__ __align__(128) char sm[32768];   // 2 bufs x (A 8KB + B 8KB)
    const int tid = threadIdx.x, lane = tid & 31, wid = tid >> 5;
    const int wm = wid & 3, wn = wid >> 2;
    const int lrow = lane & 15, lseg = lane >> 4;

    uint32_t tBase[2][2];
    tBase[0][0] = smem_u32(sm);
    tBase[0][1] = tBase[0][0] + 8192;
    tBase[1][0] = tBase[0][0] + 16384;
    tBase[1][1] = tBase[0][0] + 24576;

    auto issue = [&](int ch, int q) {
        const long k0 = (long)blockIdx.x * 2048 + ch * 64;
#pragma unroll
        for (int it = 0; it < 4; it++) {
            int t   = tid + it * 256;   // 0..1023
            int m   = t >> 9;           // 0 = G(A), 1 = W(B)
            int rem = t & 511;
            int row = rem >> 3;         // 0..63
            int kg  = rem & 7;
            const __half* src = (m ? g_Wh : g_Gh) + (size_t)row * KTOT + k0 + kg * 8;
            cpasync16(tBase[q][m] + SW128((uint32_t)(row * 128 + kg * 16)), src);
        }
    };

    float acc[4][4];
#pragma unroll
    for (int j = 0; j < 4; j++)
#pragma unroll
        for (int q = 0; q < 4; q++) acc[j][q] = 0.0f;

    issue(0, 0);
    CP_COMMIT();
    for (int ch = 0; ch < 32; ch++) {
        if (ch + 1 < 32) {
            issue(ch + 1, (ch + 1) & 1);
            CP_COMMIT();
            CP_WAIT(1);
        } else {
            CP_WAIT(0);
        }
        __syncthreads();
        uint32_t aBase = tBase[ch & 1][0], bBase = tBase[ch & 1][1];
#pragma unroll
        for (int ks = 0; ks < 4; ks++) {
            uint32_t afr[4];
            int arow = wm * 16 + lrow;
            ldsm4(afr, aBase + SW128((uint32_t)(arow * 128 + ks * 32 + lseg * 16)));
#pragma unroll
            for (int nj = 0; nj < 2; nj++) {
                uint32_t bfr[4];
                int brow = wn * 32 + nj * 16 + lrow;
                ldsm4(bfr, bBase + SW128((uint32_t)(brow * 128 + ks * 32 + lseg * 16)));
                mma_fp16(acc[nj * 2],     afr, bfr[0], bfr[2]);
                mma_fp16(acc[nj * 2 + 1], afr, bfr[1], bfr[3]);
            }
        }
        __syncthreads();
    }

    float* outp = g_Zp + (size_t)blockIdx.x * 4096;
#pragma unroll
    for (int nj = 0; nj < 4; nj++) {
        int r = wm * 16 + (lane >> 2);
        int c = wn * 32 + nj * 8 + (lane & 3) * 2;
        *(float2*)&outp[r * 64 + c]       = make_float2(acc[nj][0], acc[nj][1]);
        *(float2*)&outp[(r + 8) * 64 + c] = make_float2(acc[nj][2], acc[nj][3]);
    }
}

// ---------------------------------------------------------------------------
// Fused reduce (288 partials, 8-way split) + softmax. 64 CTAs x 512 threads.
// ---------------------------------------------------------------------------
__global__ void __launch_bounds__(512) reduce_softmax_kernel(
    const float* __restrict__ bias, float* __restrict__ out)
{
    const int b = blockIdx.x;
    const int g = threadIdx.x >> 6, n = threadIdx.x & 63;
    __shared__ float sd[8][64];
    __shared__ float red[64];

    float s = 0.0f;
#pragma unroll
    for (int u = 0; u < 36; u++)
        s += g_Zp[(size_t)(g * 36 + u) * 4096 + b * 64 + n];
    sd[g][n] = s;
    __syncthreads();

    for (int off = 4; off > 0; off >>= 1) {
        if (g < off) sd[g][n] += sd[g + off][n];
        __syncthreads();
    }

    float z = 0.0f;
    if (g == 0) {
        z = sd[0][n] * (1.0f / 196.0f) + bias[n];
        red[n] = z;
    }
    __syncthreads();
    for (int off = 32; off > 0; off >>= 1) {
        if (g == 0 && n < off) red[n] = fmaxf(red[n], red[n + off]);
        __syncthreads();
    }
    float m = red[0];
    __syncthreads();
    float e = 0.0f;
    if (g == 0) { e = expf(z - m); red[n] = e; }
    __syncthreads();
    for (int off = 32; off > 0; off >>= 1) {
        if (g == 0 && n < off) red[n] += red[n + off];
        __syncthreads();
    }
    if (g == 0) out[b * 64 + n] = e / red[0];
}

// ---------------------------------------------------------------------------
// Launch
// ---------------------------------------------------------------------------
extern "C" void kernel_launch(void* const* d_in, const int* in_sizes, int n_in,
                              void* d_out, int out_size) {
    const float* X    = (const float*)d_in[0];  // [64, 768, 14, 14]
    const float* Y    = (const float*)d_in[1];  // [64, 768, 14, 14]
    const float* w    = (const float*)d_in[2];  // [2, 64, 768, 32]
    const float* bias = (const float*)d_in[3];  // [64]
    float* out = (float*)d_out;                 // [64, 64]

    // Idempotent, not a stream op — safe under graph capture.
    cudaFuncSetAttribute(gemm_unified, cudaFuncAttributeMaxDynamicSharedMemorySize, 65536);

    // Stage 0: fp32 -> fp16 padded planes
    prep_kernel<<<13056, 256>>>(X, Y, w);

    // Stages 1+2 fused: Gram of (X,Y) and of (w0,w1) -> fp16 planes
    {
        dim3 grid(6, 6, 128);
        gemm_unified<<<grid, 256, 65536>>>();
    }

    // Stage 3: split-K contraction
    contract_kernel<<<288, 256>>>();

    // Stage 3b+4: deterministic reduce + softmax, fused
    reduce_softmax_kernel<<<64, 512>>>(bias, out);
}

// round 8
// speedup vs baseline: 7.8009x; 1.2040x over previous
#include <cuda_runtime.h>
#include <cuda_bf16.h>
#include <cuda_fp16.h>
#include <cstdint>

#define KTOT (768*768)   // 589824
#define LDK1 208         // X/Y padded K (196 -> 208)

// fp16 padded input planes
static __device__ __align__(16) __half g_Xh[(size_t)64*768*LDK1];  // 20.4 MB
static __device__ __align__(16) __half g_Yh[(size_t)64*768*LDK1];
static __device__ __align__(16) __half g_w0h[(size_t)64*768*64];   // 6.3 MB
static __device__ __align__(16) __half g_w1h[(size_t)64*768*64];
// fp16 planes of G[b,c,c'] and W[n,c,c']  (75.5 MB each)
static __device__ __align__(16) __half g_Gh[(size_t)64*KTOT];
static __device__ __align__(16) __half g_Wh[(size_t)64*KTOT];
static __device__ float g_Zp[576*64*64];   // split-K partials (deterministic)

// ---------------------------------------------------------------------------
// helpers
// ---------------------------------------------------------------------------
__device__ __forceinline__ uint32_t smem_u32(const void* p) {
    uint32_t a;
    asm("{ .reg .u64 t; cvta.to.shared.u64 t, %1; cvt.u32.u64 %0, t; }" : "=r"(a) : "l"(p));
    return a;
}
#define SW128(o) ((o) ^ (((o) >> 3) & 0x70))

__device__ __forceinline__ void cpasync16(uint32_t dst, const void* src) {
    asm volatile("cp.async.cg.shared.global [%0], [%1], 16;" :: "r"(dst), "l"(src));
}
#define CP_COMMIT() asm volatile("cp.async.commit_group;" ::: "memory")
#define CP_WAIT(n)  asm volatile("cp.async.wait_group %0;" :: "n"(n) : "memory")

__device__ __forceinline__ void ldsm4(uint32_t* r, uint32_t addr) {
    asm volatile("ldmatrix.sync.aligned.m8n8.x4.shared.b16 {%0,%1,%2,%3}, [%4];"
                 : "=r"(r[0]), "=r"(r[1]), "=r"(r[2]), "=r"(r[3]) : "r"(addr));
}
__device__ __forceinline__ void mma_fp16(float* c, const uint32_t* a, uint32_t b0, uint32_t b1) {
    asm volatile("mma.sync.aligned.m16n8k16.row.col.f32.f16.f16.f32 "
                 "{%0,%1,%2,%3}, {%4,%5,%6,%7}, {%8,%9}, {%0,%1,%2,%3};"
                 : "+f"(c[0]), "+f"(c[1]), "+f"(c[2]), "+f"(c[3])
                 : "r"(a[0]), "r"(a[1]), "r"(a[2]), "r"(a[3]), "r"(b0), "r"(b1));
}

// 128x128 warp-MMA over [128 rows][64 halves] SW128 tiles; nks k-steps of 16.
__device__ __forceinline__ void compute_chunk(
    float acc[2][8][4], uint32_t aBase, uint32_t bBase, int wm, int wn, int lane, int nks)
{
    const int lrow = lane & 15, lseg = lane >> 4;
#pragma unroll
    for (int ks = 0; ks < 4; ks++) {
        if (ks >= nks) break;
        uint32_t afr[2][4];
#pragma unroll
        for (int mi = 0; mi < 2; mi++) {
            int row = wm * 32 + mi * 16 + lrow;
            ldsm4(afr[mi], aBase + SW128((uint32_t)(row * 128 + ks * 32 + lseg * 16)));
        }
#pragma unroll
        for (int nj = 0; nj < 4; nj++) {
            uint32_t bfr[4];
            int row = wn * 64 + nj * 16 + lrow;
            ldsm4(bfr, bBase + SW128((uint32_t)(row * 128 + ks * 32 + lseg * 16)));
#pragma unroll
            for (int mi = 0; mi < 2; mi++) {
                mma_fp16(acc[mi][nj * 2],     afr[mi], bfr[0], bfr[2]);
                mma_fp16(acc[mi][nj * 2 + 1], afr[mi], bfr[1], bfr[3]);
            }
        }
    }
}

// ---------------------------------------------------------------------------
// Prep: fp32 inputs -> fp16 planes. X/Y: 196 -> 208 cols; w: 32 -> 64 cols.
// ---------------------------------------------------------------------------
__global__ void prep_kernel(const float* __restrict__ X, const float* __restrict__ Y,
                            const float* __restrict__ w)
{
    const long n1 = (long)64 * 768 * 26;   // uint4 slots per X/Y plane
    const long n3 = (long)64 * 768 * 8;    // uint4 slots per w plane
    long s = (long)blockIdx.x * 256 + threadIdx.x;
    union { __half h[8]; uint4 u; } o;
    if (s < 2 * n1) {
        const float* src = (s < n1) ? X : Y;
        __half* dst = (s < n1) ? g_Xh : g_Yh;
        long t = (s < n1) ? s : s - n1;
        long row = t / 26;
        int slot = (int)(t % 26);
        int k0 = slot * 8;
        if (slot < 23) {
            float4 p0 = *(const float4*)&src[row * 196 + k0];
            float4 p1 = *(const float4*)&src[row * 196 + k0 + 4];
            o.h[0] = __float2half(p0.x); o.h[1] = __float2half(p0.y);
            o.h[2] = __float2half(p0.z); o.h[3] = __float2half(p0.w);
            o.h[4] = __float2half(p1.x); o.h[5] = __float2half(p1.y);
            o.h[6] = __float2half(p1.z); o.h[7] = __float2half(p1.w);
        } else {
#pragma unroll
            for (int j = 0; j < 8; j++) {
                int k = k0 + j;
                o.h[j] = (k < 196) ? __float2half(src[row * 196 + k]) : __half(0.0f);
            }
        }
        *(uint4*)&dst[row * LDK1 + k0] = o.u;
    } else {
        long t = s - 2 * n1;
        const float* src = (t < n3) ? w : (w + (long)64 * 768 * 32);
        __half* dst = (t < n3) ? g_w0h : g_w1h;
        long u2 = (t < n3) ? t : t - n3;
        long row = u2 >> 3;
        int k0 = (int)(u2 & 7) << 3;
#pragma unroll
        for (int j = 0; j < 8; j++) {
            int k = k0 + j;
            o.h[j] = (k < 32) ? __float2half(src[row * 32 + k]) : __half(0.0f);
        }
        *(uint4*)&dst[row * 64 + k0] = o.u;
    }
}

// ---------------------------------------------------------------------------
// Unified Gram GEMM: grid (6,6,128), 2 CTAs/SM target.
//   bz <  64: G[bz] = Xh[bz] @ Yh[bz]^T  (ldk=208; ksteps {4,4,4,1})
//   bz >= 64: W[n]  = w0h[n] @ w1h[n]^T  (ldk=64; 1 chunk, 2 ksteps)
// dyn smem 65536 (2 bufs x (A+B 16KB)); epilogue reuses 34816 B.
// ---------------------------------------------------------------------------
__global__ void __launch_bounds__(256, 2) gemm_unified()
{
    extern __shared__ char dsm[];
    const int tid = threadIdx.x, lane = tid & 31, wid = tid >> 5;
    const int wm = wid & 3, wn = wid >> 2;
    const int bx = blockIdx.x, by = blockIdx.y, bz = blockIdx.z;
    const bool isW = bz >= 64;

    const __half* Ap;
    const __half* Bp;
    int ldk, nCh;
    if (isW) {
        const int n = bz - 64;
        Ap = g_w0h + (size_t)n * 768 * 64;
        Bp = g_w1h + (size_t)n * 768 * 64;
        ldk = 64; nCh = 1;
    } else {
        Ap = g_Xh + (size_t)bz * 768 * LDK1;
        Bp = g_Yh + (size_t)bz * 768 * LDK1;
        ldk = LDK1; nCh = 4;
    }
    const __half* Ab = Ap + (size_t)(by * 128) * ldk;
    const __half* Bb = Bp + (size_t)(bx * 128) * ldk;

    uint32_t tBase[2][2];   // [buf][A/B]
    tBase[0][0] = smem_u32(dsm);
    tBase[0][1] = tBase[0][0] + 16384;
    tBase[1][0] = tBase[0][0] + 32768;
    tBase[1][1] = tBase[0][0] + 49152;

    auto issue = [&](int ch, int q, int kgmax) {
#pragma unroll
        for (int it = 0; it < 8; it++) {
            int t   = tid + it * 256;     // 0..2047
            int m   = t >> 10;            // 0=A, 1=B
            int rem = t & 1023;
            int row = rem >> 3;
            int kg  = rem & 7;
            if (kg < kgmax) {
                const __half* src = (m ? Bb : Ab) + (size_t)row * ldk + ch * 64 + kg * 8;
                cpasync16(tBase[q][m] + SW128((uint32_t)(row * 128 + kg * 16)), src);
            }
        }
    };

    float acc[2][8][4];
#pragma unroll
    for (int i = 0; i < 2; i++)
#pragma unroll
        for (int j = 0; j < 8; j++)
#pragma unroll
            for (int q = 0; q < 4; q++) acc[i][j][q] = 0.0f;

    issue(0, 0, isW ? 4 : 8);
    CP_COMMIT();
    for (int ch = 0; ch < nCh; ch++) {
        if (ch + 1 < nCh) {
            issue(ch + 1, (ch + 1) & 1, (ch + 1 < 3) ? 8 : 2);
            CP_COMMIT();
            CP_WAIT(1);
        } else {
            CP_WAIT(0);
        }
        __syncthreads();
        int nks = isW ? 2 : (ch < 3 ? 4 : 1);
        compute_chunk(acc, tBase[ch & 1][0], tBase[ch & 1][1], wm, wn, lane, nks);
        __syncthreads();
    }

    // epilogue: fragments -> half2 -> smem fp16 [128][68 u32 pitch] -> global
    uint32_t* Sh = (uint32_t*)dsm;
#pragma unroll
    for (int mi = 0; mi < 2; mi++)
#pragma unroll
        for (int ni = 0; ni < 8; ni++) {
            int r  = wm * 32 + mi * 16 + (lane >> 2);
            int c2 = wn * 32 + ni * 4 + (lane & 3);
            __half2 h0 = __floats2half2_rn(acc[mi][ni][0], acc[mi][ni][1]);
            __half2 h1 = __floats2half2_rn(acc[mi][ni][2], acc[mi][ni][3]);
            Sh[r * 68 + c2]       = *(uint32_t*)&h0;
            Sh[(r + 8) * 68 + c2] = *(uint32_t*)&h1;
        }
    __syncthreads();

    __half* Oh = (isW ? g_Wh : g_Gh) + (size_t)(bz & 63) * KTOT;
#pragma unroll
    for (int it = 0; it < 8; it++) {
        int idx = tid + it * 256;      // 2048 uint4 = 128 rows x 16
        int row = idx >> 4;
        int c4  = (idx & 15) * 4;
        uint4 v = *(const uint4*)&Sh[row * 68 + c4];
        *(uint4*)&Oh[(size_t)(by * 128 + row) * 768 + bx * 128 + c4 * 2] = v;
    }
}

// ---------------------------------------------------------------------------
// Stage 3: split-K contraction, 64x64 output per CTA.
// 576 CTAs x 1024-k slices, 16 chunks of 64, 3-stage cp.async pipeline.
// smem 48KB static -> ~4 CTAs/SM.
// ---------------------------------------------------------------------------
__global__ void __launch_bounds__(256) contract_kernel()
{
    __shared__ __align__(128) char sm[49152];   // 3 bufs x (A 8KB + B 8KB)
    const int tid = threadIdx.x, lane = tid & 31, wid = tid >> 5;
    const int wm = wid & 3, wn = wid >> 2;
    const int lrow = lane & 15, lseg = lane >> 4;

    uint32_t tBase[3][2];
#pragma unroll
    for (int q = 0; q < 3; q++) {
        tBase[q][0] = smem_u32(sm) + q * 16384;
        tBase[q][1] = tBase[q][0] + 8192;
    }

    auto issue = [&](int ch, int q) {
        const long k0 = (long)blockIdx.x * 1024 + ch * 64;
#pragma unroll
        for (int it = 0; it < 4; it++) {
            int t   = tid + it * 256;   // 0..1023
            int m   = t >> 9;           // 0 = G(A), 1 = W(B)
            int rem = t & 511;
            int row = rem >> 3;         // 0..63
            int kg  = rem & 7;
            const __half* src = (m ? g_Wh : g_Gh) + (size_t)row * KTOT + k0 + kg * 8;
            cpasync16(tBase[q][m] + SW128((uint32_t)(row * 128 + kg * 16)), src);
        }
    };

    float acc[4][4];
#pragma unroll
    for (int j = 0; j < 4; j++)
#pragma unroll
        for (int q = 0; q < 4; q++) acc[j][q] = 0.0f;

    issue(0, 0); CP_COMMIT();
    issue(1, 1); CP_COMMIT();
    for (int ch = 0; ch < 16; ch++) {
        if (ch + 2 < 16) {
            issue(ch + 2, (ch + 2) % 3);
            CP_COMMIT();
            CP_WAIT(2);
        } else if (ch + 1 < 16) {
            CP_WAIT(1);
        } else {
            CP_WAIT(0);
        }
        __syncthreads();
        uint32_t aBase = tBase[ch % 3][0], bBase = tBase[ch % 3][1];
#pragma unroll
        for (int ks = 0; ks < 4; ks++) {
            uint32_t afr[4];
            int arow = wm * 16 + lrow;
            ldsm4(afr, aBase + SW128((uint32_t)(arow * 128 + ks * 32 + lseg * 16)));
#pragma unroll
            for (int nj = 0; nj < 2; nj++) {
                uint32_t bfr[4];
                int brow = wn * 32 + nj * 16 + lrow;
                ldsm4(bfr, bBase + SW128((uint32_t)(brow * 128 + ks * 32 + lseg * 16)));
                mma_fp16(acc[nj * 2],     afr, bfr[0], bfr[2]);
                mma_fp16(acc[nj * 2 + 1], afr, bfr[1], bfr[3]);
            }
        }
        __syncthreads();
    }

    float* outp = g_Zp + (size_t)blockIdx.x * 4096;
#pragma unroll
    for (int nj = 0; nj < 4; nj++) {
        int r = wm * 16 + (lane >> 2);
        int c = wn * 32 + nj * 8 + (lane & 3) * 2;
        *(float2*)&outp[r * 64 + c]       = make_float2(acc[nj][0], acc[nj][1]);
        *(float2*)&outp[(r + 8) * 64 + c] = make_float2(acc[nj][2], acc[nj][3]);
    }
}

// ---------------------------------------------------------------------------
// Fused reduce (576 partials, 8-way split) + softmax. 64 CTAs x 512 threads.
// ---------------------------------------------------------------------------
__global__ void __launch_bounds__(512) reduce_softmax_kernel(
    const float* __restrict__ bias, float* __restrict__ out)
{
    const int b = blockIdx.x;
    const int g = threadIdx.x >> 6, n = threadIdx.x & 63;
    __shared__ float sd[8][64];
    __shared__ float red[64];

    float s = 0.0f;
#pragma unroll 8
    for (int u = 0; u < 72; u++)
        s += g_Zp[(size_t)(g * 72 + u) * 4096 + b * 64 + n];
    sd[g][n] = s;
    __syncthreads();

    for (int off = 4; off > 0; off >>= 1) {
        if (g < off) sd[g][n] += sd[g + off][n];
        __syncthreads();
    }

    float z = 0.0f;
    if (g == 0) {
        z = sd[0][n] * (1.0f / 196.0f) + bias[n];
        red[n] = z;
    }
    __syncthreads();
    for (int off = 32; off > 0; off >>= 1) {
        if (g == 0 && n < off) red[n] = fmaxf(red[n], red[n + off]);
        __syncthreads();
    }
    float m = red[0];
    __syncthreads();
    float e = 0.0f;
    if (g == 0) { e = expf(z - m); red[n] = e; }
    __syncthreads();
    for (int off = 32; off > 0; off >>= 1) {
        if (g == 0 && n < off) red[n] += red[n + off];
        __syncthreads();
    }
    if (g == 0) out[b * 64 + n] = e / red[0];
}

// ---------------------------------------------------------------------------
// Launch
// ---------------------------------------------------------------------------
extern "C" void kernel_launch(void* const* d_in, const int* in_sizes, int n_in,
                              void* d_out, int out_size) {
    const float* X    = (const float*)d_in[0];  // [64, 768, 14, 14]
    const float* Y    = (const float*)d_in[1];  // [64, 768, 14, 14]
    const float* w    = (const float*)d_in[2];  // [2, 64, 768, 32]
    const float* bias = (const float*)d_in[3];  // [64]
    float* out = (float*)d_out;                 // [64, 64]

    // Idempotent, not a stream op — safe under graph capture.
    cudaFuncSetAttribute(gemm_unified, cudaFuncAttributeMaxDynamicSharedMemorySize, 65536);

    // Stage 0: fp32 -> fp16 padded planes
    prep_kernel<<<13056, 256>>>(X, Y, w);

    // Stages 1+2 fused: Gram of (X,Y) and of (w0,w1) -> fp16 planes
    {
        dim3 grid(6, 6, 128);
        gemm_unified<<<grid, 256, 65536>>>();
    }

    // Stage 3: split-K contraction
    contract_kernel<<<576, 256>>>();

    // Stage 3b+4: deterministic reduce + softmax, fused
    reduce_softmax_kernel<<<64, 512>>>(bias, out);
}

// round 9
// speedup vs baseline: 7.9577x; 1.0201x over previous
#include <cuda_runtime.h>
#include <cuda_bf16.h>
#include <cuda_fp16.h>
#include <cstdint>

#define KTOT (768*768)   // 589824
#define LDK1 208         // X/Y padded K (196 -> 208)

// fp16 input planes
static __device__ __align__(16) __half g_Xh[(size_t)64*768*LDK1];  // 20.4 MB
static __device__ __align__(16) __half g_Yh[(size_t)64*768*LDK1];
static __device__ __align__(16) __half g_w0h[(size_t)64*768*32];   // 3.1 MB, unpadded
static __device__ __align__(16) __half g_w1h[(size_t)64*768*32];
// fp16 planes of G[b,c,c'] and W[n,c,c']  (75.5 MB each)
static __device__ __align__(16) __half g_Gh[(size_t)64*KTOT];
static __device__ __align__(16) __half g_Wh[(size_t)64*KTOT];
static __device__ float g_Zp[576*64*64];   // split-K partials (deterministic)
static __device__ float g_Z[64*64];

// ---------------------------------------------------------------------------
// helpers
// ---------------------------------------------------------------------------
__device__ __forceinline__ uint32_t smem_u32(const void* p) {
    uint32_t a;
    asm("{ .reg .u64 t; cvta.to.shared.u64 t, %1; cvt.u32.u64 %0, t; }" : "=r"(a) : "l"(p));
    return a;
}
#define SW128(o) ((o) ^ (((o) >> 3) & 0x70))

__device__ __forceinline__ void cpasync16(uint32_t dst, const void* src) {
    asm volatile("cp.async.cg.shared.global [%0], [%1], 16;" :: "r"(dst), "l"(src));
}
#define CP_COMMIT() asm volatile("cp.async.commit_group;" ::: "memory")
#define CP_WAIT(n)  asm volatile("cp.async.wait_group %0;" :: "n"(n) : "memory")

__device__ __forceinline__ void ldsm4(uint32_t* r, uint32_t addr) {
    asm volatile("ldmatrix.sync.aligned.m8n8.x4.shared.b16 {%0,%1,%2,%3}, [%4];"
                 : "=r"(r[0]), "=r"(r[1]), "=r"(r[2]), "=r"(r[3]) : "r"(addr));
}
__device__ __forceinline__ void mma_fp16(float* c, const uint32_t* a, uint32_t b0, uint32_t b1) {
    asm volatile("mma.sync.aligned.m16n8k16.row.col.f32.f16.f16.f32 "
                 "{%0,%1,%2,%3}, {%4,%5,%6,%7}, {%8,%9}, {%0,%1,%2,%3};"
                 : "+f"(c[0]), "+f"(c[1]), "+f"(c[2]), "+f"(c[3])
                 : "r"(a[0]), "r"(a[1]), "r"(a[2]), "r"(a[3]), "r"(b0), "r"(b1));
}

// 128x128 warp-MMA over [128 rows][64 halves] SW128 tiles; nks k-steps of 16.
__device__ __forceinline__ void compute_chunk(
    float acc[2][8][4], uint32_t aBase, uint32_t bBase, int wm, int wn, int lane, int nks)
{
    const int lrow = lane & 15, lseg = lane >> 4;
#pragma unroll
    for (int ks = 0; ks < 4; ks++) {
        if (ks >= nks) break;
        uint32_t afr[2][4];
#pragma unroll
        for (int mi = 0; mi < 2; mi++) {
            int row = wm * 32 + mi * 16 + lrow;
            ldsm4(afr[mi], aBase + SW128((uint32_t)(row * 128 + ks * 32 + lseg * 16)));
        }
#pragma unroll
        for (int nj = 0; nj < 4; nj++) {
            uint32_t bfr[4];
            int row = wn * 64 + nj * 16 + lrow;
            ldsm4(bfr, bBase + SW128((uint32_t)(row * 128 + ks * 32 + lseg * 16)));
#pragma unroll
            for (int mi = 0; mi < 2; mi++) {
                mma_fp16(acc[mi][nj * 2],     afr[mi], bfr[0], bfr[2]);
                mma_fp16(acc[mi][nj * 2 + 1], afr[mi], bfr[1], bfr[3]);
            }
        }
    }
}

// ---------------------------------------------------------------------------
// Prep: fp32 -> fp16 planes. X/Y: 196 -> 208 cols; w: 32 cols unpadded.
// grid 11520 x 256 (exact).
// ---------------------------------------------------------------------------
__global__ void prep_kernel(const float* __restrict__ X, const float* __restrict__ Y,
                            const float* __restrict__ w)
{
    const long n1 = (long)64 * 768 * 26;   // uint4 slots per X/Y plane
    const long n3 = (long)64 * 768 * 4;    // uint4 slots per w plane (32 cols)
    long s = (long)blockIdx.x * 256 + threadIdx.x;
    union { __half h[8]; uint4 u; } o;
    if (s < 2 * n1) {
        const float* src = (s < n1) ? X : Y;
        __half* dst = (s < n1) ? g_Xh : g_Yh;
        long t = (s < n1) ? s : s - n1;
        long row = t / 26;
        int slot = (int)(t % 26);
        int k0 = slot * 8;
        if (slot < 23) {
            float4 p0 = *(const float4*)&src[row * 196 + k0];
            float4 p1 = *(const float4*)&src[row * 196 + k0 + 4];
            o.h[0] = __float2half(p0.x); o.h[1] = __float2half(p0.y);
            o.h[2] = __float2half(p0.z); o.h[3] = __float2half(p0.w);
            o.h[4] = __float2half(p1.x); o.h[5] = __float2half(p1.y);
            o.h[6] = __float2half(p1.z); o.h[7] = __float2half(p1.w);
        } else {
#pragma unroll
            for (int j = 0; j < 8; j++) {
                int k = k0 + j;
                o.h[j] = (k < 196) ? __float2half(src[row * 196 + k]) : __half(0.0f);
            }
        }
        *(uint4*)&dst[row * LDK1 + k0] = o.u;
    } else {
        long t = s - 2 * n1;
        const float* src = (t < n3) ? w : (w + (long)64 * 768 * 32);
        __half* dst = (t < n3) ? g_w0h : g_w1h;
        long u2 = (t < n3) ? t : t - n3;
        long row = u2 >> 2;
        int k0 = (int)(u2 & 3) << 3;
        float4 p0 = *(const float4*)&src[row * 32 + k0];
        float4 p1 = *(const float4*)&src[row * 32 + k0 + 4];
        o.h[0] = __float2half(p0.x); o.h[1] = __float2half(p0.y);
        o.h[2] = __float2half(p0.z); o.h[3] = __float2half(p0.w);
        o.h[4] = __float2half(p1.x); o.h[5] = __float2half(p1.y);
        o.h[6] = __float2half(p1.z); o.h[7] = __float2half(p1.w);
        *(uint4*)&dst[row * 32 + k0] = o.u;
    }
}

// ---------------------------------------------------------------------------
// Unified Gram GEMM: grid (6,6,128), 2 CTAs/SM.
//   bz <  64: G[bz] = Xh[bz] @ Yh[bz]^T  (ldk=208; 4 chunks, ksteps {4,4,4,1})
//   bz >= 64: W[n]  = w0h[n] @ w1h[n]^T  (ldk=32; 1 chunk, 2 ksteps)
// 3-stage cp.async pipeline; dyn smem 98304 (3 bufs x (A+B 16KB)).
// ---------------------------------------------------------------------------
__global__ void __launch_bounds__(256, 2) gemm_unified()
{
    extern __shared__ char dsm[];
    const int tid = threadIdx.x, lane = tid & 31, wid = tid >> 5;
    const int wm = wid & 3, wn = wid >> 2;
    const int bx = blockIdx.x, by = blockIdx.y, bz = blockIdx.z;
    const bool isW = bz >= 64;

    const __half* Ap;
    const __half* Bp;
    int ldk, nCh;
    if (isW) {
        const int n = bz - 64;
        Ap = g_w0h + (size_t)n * 768 * 32;
        Bp = g_w1h + (size_t)n * 768 * 32;
        ldk = 32; nCh = 1;
    } else {
        Ap = g_Xh + (size_t)bz * 768 * LDK1;
        Bp = g_Yh + (size_t)bz * 768 * LDK1;
        ldk = LDK1; nCh = 4;
    }
    const __half* Ab = Ap + (size_t)(by * 128) * ldk;
    const __half* Bb = Bp + (size_t)(bx * 128) * ldk;

    uint32_t tBase[3][2];   // [buf][A/B]
#pragma unroll
    for (int q = 0; q < 3; q++) {
        tBase[q][0] = smem_u32(dsm) + q * 32768;
        tBase[q][1] = tBase[q][0] + 16384;
    }

    auto issue = [&](int ch, int q, int kgmax) {
#pragma unroll
        for (int it = 0; it < 8; it++) {
            int t   = tid + it * 256;     // 0..2047
            int m   = t >> 10;            // 0=A, 1=B
            int rem = t & 1023;
            int row = rem >> 3;
            int kg  = rem & 7;
            if (kg < kgmax) {
                const __half* src = (m ? Bb : Ab) + (size_t)row * ldk + ch * 64 + kg * 8;
                cpasync16(tBase[q][m] + SW128((uint32_t)(row * 128 + kg * 16)), src);
            }
        }
    };

    float acc[2][8][4];
#pragma unroll
    for (int i = 0; i < 2; i++)
#pragma unroll
        for (int j = 0; j < 8; j++)
#pragma unroll
            for (int q = 0; q < 4; q++) acc[i][j][q] = 0.0f;

    // pipeline prologue: prefetch up to 2 chunks
    issue(0, 0, isW ? 4 : 8);
    CP_COMMIT();
    if (nCh > 1) { issue(1, 1, 8); CP_COMMIT(); }

    for (int ch = 0; ch < nCh; ch++) {
        if (ch + 2 < nCh) {
            issue(ch + 2, (ch + 2) % 3, (ch + 2 < 3) ? 8 : 2);
            CP_COMMIT();
            CP_WAIT(2);
        } else if (ch + 1 < nCh) {
            CP_WAIT(1);
        } else {
            CP_WAIT(0);
        }
        __syncthreads();
        int nks = isW ? 2 : (ch < 3 ? 4 : 1);
        compute_chunk(acc, tBase[ch % 3][0], tBase[ch % 3][1], wm, wn, lane, nks);
        __syncthreads();
    }

    // epilogue: fragments -> half2 -> smem fp16 [128][68 u32 pitch] -> global
    uint32_t* Sh = (uint32_t*)dsm;
#pragma unroll
    for (int mi = 0; mi < 2; mi++)
#pragma unroll
        for (int ni = 0; ni < 8; ni++) {
            int r  = wm * 32 + mi * 16 + (lane >> 2);
            int c2 = wn * 32 + ni * 4 + (lane & 3);
            __half2 h0 = __floats2half2_rn(acc[mi][ni][0], acc[mi][ni][1]);
            __half2 h1 = __floats2half2_rn(acc[mi][ni][2], acc[mi][ni][3]);
            Sh[r * 68 + c2]       = *(uint32_t*)&h0;
            Sh[(r + 8) * 68 + c2] = *(uint32_t*)&h1;
        }
    __syncthreads();

    __half* Oh = (isW ? g_Wh : g_Gh) + (size_t)(bz & 63) * KTOT;
#pragma unroll
    for (int it = 0; it < 8; it++) {
        int idx = tid + it * 256;      // 2048 uint4 = 128 rows x 16
        int row = idx >> 4;
        int c4  = (idx & 15) * 4;
        uint4 v = *(const uint4*)&Sh[row * 68 + c4];
        *(uint4*)&Oh[(size_t)(by * 128 + row) * 768 + bx * 128 + c4 * 2] = v;
    }
}

// ---------------------------------------------------------------------------
// Stage 3: split-K contraction, 64x64 output per CTA.
// 576 CTAs x 1024-k slices, 16 chunks of 64, 3-stage cp.async pipeline.
// ---------------------------------------------------------------------------
__global__ void __launch_bounds__(256) contract_kernel()
{
    __shared__ __align__(128) char sm[49152];   // 3 bufs x (A 8KB + B 8KB)
    const int tid = threadIdx.x, lane = tid & 31, wid = tid >> 5;
    const int wm = wid & 3, wn = wid >> 2;
    const int lrow = lane & 15, lseg = lane >> 4;

    uint32_t tBase[3][2];
#pragma unroll
    for (int q = 0; q < 3; q++) {
        tBase[q][0] = smem_u32(sm) + q * 16384;
        tBase[q][1] = tBase[q][0] + 8192;
    }

    auto issue = [&](int ch, int q) {
        const long k0 = (long)blockIdx.x * 1024 + ch * 64;
#pragma unroll
        for (int it = 0; it < 4; it++) {
            int t   = tid + it * 256;   // 0..1023
            int m   = t >> 9;           // 0 = G(A), 1 = W(B)
            int rem = t & 511;
            int row = rem >> 3;         // 0..63
            int kg  = rem & 7;
            const __half* src = (m ? g_Wh : g_Gh) + (size_t)row * KTOT + k0 + kg * 8;
            cpasync16(tBase[q][m] + SW128((uint32_t)(row * 128 + kg * 16)), src);
        }
    };

    float acc[4][4];
#pragma unroll
    for (int j = 0; j < 4; j++)
#pragma unroll
        for (int q = 0; q < 4; q++) acc[j][q] = 0.0f;

    issue(0, 0); CP_COMMIT();
    issue(1, 1); CP_COMMIT();
    for (int ch = 0; ch < 16; ch++) {
        if (ch + 2 < 16) {
            issue(ch + 2, (ch + 2) % 3);
            CP_COMMIT();
            CP_WAIT(2);
        } else if (ch + 1 < 16) {
            CP_WAIT(1);
        } else {
            CP_WAIT(0);
        }
        __syncthreads();
        uint32_t aBase = tBase[ch % 3][0], bBase = tBase[ch % 3][1];
#pragma unroll
        for (int ks = 0; ks < 4; ks++) {
            uint32_t afr[4];
            int arow = wm * 16 + lrow;
            ldsm4(afr, aBase + SW128((uint32_t)(arow * 128 + ks * 32 + lseg * 16)));
#pragma unroll
            for (int nj = 0; nj < 2; nj++) {
                uint32_t bfr[4];
                int brow = wn * 32 + nj * 16 + lrow;
                ldsm4(bfr, bBase + SW128((uint32_t)(brow * 128 + ks * 32 + lseg * 16)));
                mma_fp16(acc[nj * 2],     afr, bfr[0], bfr[2]);
                mma_fp16(acc[nj * 2 + 1], afr, bfr[1], bfr[3]);
            }
        }
        __syncthreads();
    }

    float* outp = g_Zp + (size_t)blockIdx.x * 4096;
#pragma unroll
    for (int nj = 0; nj < 4; nj++) {
        int r = wm * 16 + (lane >> 2);
        int c = wn * 32 + nj * 8 + (lane & 3) * 2;
        *(float2*)&outp[r * 64 + c]       = make_float2(acc[nj][0], acc[nj][1]);
        *(float2*)&outp[(r + 8) * 64 + c] = make_float2(acc[nj][2], acc[nj][3]);
    }
}

// ---------------------------------------------------------------------------
// Stage 3b: deterministic reduce of 576 partials. grid 256 x 256:
// 16 outputs/CTA, 16 threads/output x 36 loads + smem tree.
// ---------------------------------------------------------------------------
__global__ void reduce_z_kernel() {
    __shared__ float sd[256];
    const int il = threadIdx.x & 15, jt = threadIdx.x >> 4;
    const int i = blockIdx.x * 16 + il;
    float s = 0.0f;
#pragma unroll
    for (int u = 0; u < 36; u++)
        s += g_Zp[(size_t)(jt + u * 16) * 4096 + i];
    sd[threadIdx.x] = s;
    __syncthreads();
    for (int off = 8; off; off >>= 1) {
        if (jt < off) sd[threadIdx.x] += sd[threadIdx.x + off * 16];
        __syncthreads();
    }
    if (jt == 0) g_Z[i] = sd[il];
}

// ---------------------------------------------------------------------------
// Stage 4: softmax over n of z/196 + bias
// ---------------------------------------------------------------------------
__global__ void softmax_kernel(const float* __restrict__ bias, float* __restrict__ out) {
    const int b = blockIdx.x, n = threadIdx.x;
    __shared__ float red[64];
    float v = g_Z[b * 64 + n] * (1.0f / 196.0f) + bias[n];
    red[n] = v;
    __syncthreads();
    for (int s = 32; s > 0; s >>= 1) { if (n < s) red[n] = fmaxf(red[n], red[n + s]); __syncthreads(); }
    float m = red[0];
    __syncthreads();
    float e = expf(v - m);
    red[n] = e;
    __syncthreads();
    for (int s = 32; s > 0; s >>= 1) { if (n < s) red[n] += red[n + s]; __syncthreads(); }
    out[b * 64 + n] = e / red[0];
}

// ---------------------------------------------------------------------------
// Launch
// ---------------------------------------------------------------------------
extern "C" void kernel_launch(void* const* d_in, const int* in_sizes, int n_in,
                              void* d_out, int out_size) {
    const float* X    = (const float*)d_in[0];  // [64, 768, 14, 14]
    const float* Y    = (const float*)d_in[1];  // [64, 768, 14, 14]
    const float* w    = (const float*)d_in[2];  // [2, 64, 768, 32]
    const float* bias = (const float*)d_in[3];  // [64]
    float* out = (float*)d_out;                 // [64, 64]

    // Idempotent, not a stream op — safe under graph capture.
    cudaFuncSetAttribute(gemm_unified, cudaFuncAttributeMaxDynamicSharedMemorySize, 98304);

    // Stage 0: fp32 -> fp16 planes
    prep_kernel<<<11520, 256>>>(X, Y, w);

    // Stages 1+2 fused: Gram of (X,Y) and of (w0,w1) -> fp16 planes
    {
        dim3 grid(6, 6, 128);
        gemm_unified<<<grid, 256, 98304>>>();
    }

    // Stage 3: split-K contraction + deterministic reduce
    contract_kernel<<<576, 256>>>();
    reduce_z_kernel<<<256, 256>>>();

    // Stage 4: softmax
    softmax_kernel<<<64, 64>>>(bias, out);
}

// round 10
// speedup vs baseline: 7.9741x; 1.0021x over previous
#include <cuda_runtime.h>
#include <cuda_bf16.h>
#include <cuda_fp16.h>
#include <cstdint>

#define KTOT (768*768)   // 589824
#define LDK1 208         // X/Y padded K (196 -> 208)

// fp16 input planes
static __device__ __align__(16) __half g_Xh[(size_t)64*768*LDK1];  // 20.4 MB
static __device__ __align__(16) __half g_Yh[(size_t)64*768*LDK1];
static __device__ __align__(16) __half g_w0h[(size_t)64*768*32];   // 3.1 MB, unpadded
static __device__ __align__(16) __half g_w1h[(size_t)64*768*32];
// fp16 planes of G[b,c,c'] and W[n,c,c']  (75.5 MB each)
static __device__ __align__(16) __half g_Gh[(size_t)64*KTOT];
static __device__ __align__(16) __half g_Wh[(size_t)64*KTOT];
static __device__ float g_Zp[576*64*64];   // split-K partials (deterministic)
static __device__ float g_Z[64*64];

// ---------------------------------------------------------------------------
// helpers
// ---------------------------------------------------------------------------
__device__ __forceinline__ uint32_t smem_u32(const void* p) {
    uint32_t a;
    asm("{ .reg .u64 t; cvta.to.shared.u64 t, %1; cvt.u32.u64 %0, t; }" : "=r"(a) : "l"(p));
    return a;
}
#define SW128(o) ((o) ^ (((o) >> 3) & 0x70))

__device__ __forceinline__ void cpasync16(uint32_t dst, const void* src) {
    asm volatile("cp.async.cg.shared.global [%0], [%1], 16;" :: "r"(dst), "l"(src));
}
#define CP_COMMIT() asm volatile("cp.async.commit_group;" ::: "memory")
#define CP_WAIT(n)  asm volatile("cp.async.wait_group %0;" :: "n"(n) : "memory")

__device__ __forceinline__ void ldsm4(uint32_t* r, uint32_t addr) {
    asm volatile("ldmatrix.sync.aligned.m8n8.x4.shared.b16 {%0,%1,%2,%3}, [%4];"
                 : "=r"(r[0]), "=r"(r[1]), "=r"(r[2]), "=r"(r[3]) : "r"(addr));
}
__device__ __forceinline__ void mma_fp16(float* c, const uint32_t* a, uint32_t b0, uint32_t b1) {
    asm volatile("mma.sync.aligned.m16n8k16.row.col.f32.f16.f16.f32 "
                 "{%0,%1,%2,%3}, {%4,%5,%6,%7}, {%8,%9}, {%0,%1,%2,%3};"
                 : "+f"(c[0]), "+f"(c[1]), "+f"(c[2]), "+f"(c[3])
                 : "r"(a[0]), "r"(a[1]), "r"(a[2]), "r"(a[3]), "r"(b0), "r"(b1));
}

// 128x128 warp-MMA over [128 rows][64 halves] SW128 tiles; nks k-steps of 16.
__device__ __forceinline__ void compute_chunk(
    float acc[2][8][4], uint32_t aBase, uint32_t bBase, int wm, int wn, int lane, int nks)
{
    const int lrow = lane & 15, lseg = lane >> 4;
#pragma unroll
    for (int ks = 0; ks < 4; ks++) {
        if (ks >= nks) break;
        uint32_t afr[2][4];
#pragma unroll
        for (int mi = 0; mi < 2; mi++) {
            int row = wm * 32 + mi * 16 + lrow;
            ldsm4(afr[mi], aBase + SW128((uint32_t)(row * 128 + ks * 32 + lseg * 16)));
        }
#pragma unroll
        for (int nj = 0; nj < 4; nj++) {
            uint32_t bfr[4];
            int row = wn * 64 + nj * 16 + lrow;
            ldsm4(bfr, bBase + SW128((uint32_t)(row * 128 + ks * 32 + lseg * 16)));
#pragma unroll
            for (int mi = 0; mi < 2; mi++) {
                mma_fp16(acc[mi][nj * 2],     afr[mi], bfr[0], bfr[2]);
                mma_fp16(acc[mi][nj * 2 + 1], afr[mi], bfr[1], bfr[3]);
            }
        }
    }
}

// ---------------------------------------------------------------------------
// Prep: fp32 -> fp16 planes. X/Y: 196 -> 208 cols; w: 32 cols unpadded.
// grid 11520 x 256 (exact).
// ---------------------------------------------------------------------------
__global__ void prep_kernel(const float* __restrict__ X, const float* __restrict__ Y,
                            const float* __restrict__ w)
{
    const long n1 = (long)64 * 768 * 26;   // uint4 slots per X/Y plane
    const long n3 = (long)64 * 768 * 4;    // uint4 slots per w plane (32 cols)
    long s = (long)blockIdx.x * 256 + threadIdx.x;
    union { __half h[8]; uint4 u; } o;
    if (s < 2 * n1) {
        const float* src = (s < n1) ? X : Y;
        __half* dst = (s < n1) ? g_Xh : g_Yh;
        long t = (s < n1) ? s : s - n1;
        long row = t / 26;
        int slot = (int)(t % 26);
        int k0 = slot * 8;
        if (slot < 23) {
            float4 p0 = *(const float4*)&src[row * 196 + k0];
            float4 p1 = *(const float4*)&src[row * 196 + k0 + 4];
            o.h[0] = __float2half(p0.x); o.h[1] = __float2half(p0.y);
            o.h[2] = __float2half(p0.z); o.h[3] = __float2half(p0.w);
            o.h[4] = __float2half(p1.x); o.h[5] = __float2half(p1.y);
            o.h[6] = __float2half(p1.z); o.h[7] = __float2half(p1.w);
        } else {
#pragma unroll
            for (int j = 0; j < 8; j++) {
                int k = k0 + j;
                o.h[j] = (k < 196) ? __float2half(src[row * 196 + k]) : __half(0.0f);
            }
        }
        *(uint4*)&dst[row * LDK1 + k0] = o.u;
    } else {
        long t = s - 2 * n1;
        const float* src = (t < n3) ? w : (w + (long)64 * 768 * 32);
        __half* dst = (t < n3) ? g_w0h : g_w1h;
        long u2 = (t < n3) ? t : t - n3;
        long row = u2 >> 2;
        int k0 = (int)(u2 & 3) << 3;
        float4 p0 = *(const float4*)&src[row * 32 + k0];
        float4 p1 = *(const float4*)&src[row * 32 + k0 + 4];
        o.h[0] = __float2half(p0.x); o.h[1] = __float2half(p0.y);
        o.h[2] = __float2half(p0.z); o.h[3] = __float2half(p0.w);
        o.h[4] = __float2half(p1.x); o.h[5] = __float2half(p1.y);
        o.h[6] = __float2half(p1.z); o.h[7] = __float2half(p1.w);
        *(uint4*)&dst[row * 32 + k0] = o.u;
    }
}

// ---------------------------------------------------------------------------
// Unified Gram GEMM: grid (6,6,128), 2 CTAs/SM, G/W wave-interleaved:
//   bz even: G[bz/2] = Xh @ Yh^T (ldk=208; 4 chunks, ksteps {4,4,4,1})
//   bz odd : W[bz/2] = w0h @ w1h^T (ldk=32; 1 chunk, 2 ksteps)
// MMA-heavy G CTAs and store-heavy W CTAs mix within every wave.
// 3-stage cp.async pipeline; dyn smem 98304.
// ---------------------------------------------------------------------------
__global__ void __launch_bounds__(256, 2) gemm_unified()
{
    extern __shared__ char dsm[];
    const int tid = threadIdx.x, lane = tid & 31, wid = tid >> 5;
    const int wm = wid & 3, wn = wid >> 2;
    const int bx = blockIdx.x, by = blockIdx.y, bzr = blockIdx.z;
    const bool isW = (bzr & 1);
    const int  idx = bzr >> 1;        // batch b (G) or output n (W)

    const __half* Ap;
    const __half* Bp;
    int ldk, nCh;
    if (isW) {
        Ap = g_w0h + (size_t)idx * 768 * 32;
        Bp = g_w1h + (size_t)idx * 768 * 32;
        ldk = 32; nCh = 1;
    } else {
        Ap = g_Xh + (size_t)idx * 768 * LDK1;
        Bp = g_Yh + (size_t)idx * 768 * LDK1;
        ldk = LDK1; nCh = 4;
    }
    const __half* Ab = Ap + (size_t)(by * 128) * ldk;
    const __half* Bb = Bp + (size_t)(bx * 128) * ldk;

    uint32_t tBase[3][2];   // [buf][A/B]
#pragma unroll
    for (int q = 0; q < 3; q++) {
        tBase[q][0] = smem_u32(dsm) + q * 32768;
        tBase[q][1] = tBase[q][0] + 16384;
    }

    auto issue = [&](int ch, int q, int kgmax) {
#pragma unroll
        for (int it = 0; it < 8; it++) {
            int t   = tid + it * 256;     // 0..2047
            int m   = t >> 10;            // 0=A, 1=B
            int rem = t & 1023;
            int row = rem >> 3;
            int kg  = rem & 7;
            if (kg < kgmax) {
                const __half* src = (m ? Bb : Ab) + (size_t)row * ldk + ch * 64 + kg * 8;
                cpasync16(tBase[q][m] + SW128((uint32_t)(row * 128 + kg * 16)), src);
            }
        }
    };

    float acc[2][8][4];
#pragma unroll
    for (int i = 0; i < 2; i++)
#pragma unroll
        for (int j = 0; j < 8; j++)
#pragma unroll
            for (int q = 0; q < 4; q++) acc[i][j][q] = 0.0f;

    // pipeline prologue: prefetch up to 2 chunks
    issue(0, 0, isW ? 4 : 8);
    CP_COMMIT();
    if (nCh > 1) { issue(1, 1, 8); CP_COMMIT(); }

    for (int ch = 0; ch < nCh; ch++) {
        if (ch + 2 < nCh) {
            issue(ch + 2, (ch + 2) % 3, (ch + 2 < 3) ? 8 : 2);
            CP_COMMIT();
            CP_WAIT(2);
        } else if (ch + 1 < nCh) {
            CP_WAIT(1);
        } else {
            CP_WAIT(0);
        }
        __syncthreads();
        int nks = isW ? 2 : (ch < 3 ? 4 : 1);
        compute_chunk(acc, tBase[ch % 3][0], tBase[ch % 3][1], wm, wn, lane, nks);
        __syncthreads();
    }

    // epilogue: fragments -> half2 -> smem fp16 [128][68 u32 pitch] -> global
    uint32_t* Sh = (uint32_t*)dsm;
#pragma unroll
    for (int mi = 0; mi < 2; mi++)
#pragma unroll
        for (int ni = 0; ni < 8; ni++) {
            int r  = wm * 32 + mi * 16 + (lane >> 2);
            int c2 = wn * 32 + ni * 4 + (lane & 3);
            __half2 h0 = __floats2half2_rn(acc[mi][ni][0], acc[mi][ni][1]);
            __half2 h1 = __floats2half2_rn(acc[mi][ni][2], acc[mi][ni][3]);
            Sh[r * 68 + c2]       = *(uint32_t*)&h0;
            Sh[(r + 8) * 68 + c2] = *(uint32_t*)&h1;
        }
    __syncthreads();

    __half* Oh = (isW ? g_Wh : g_Gh) + (size_t)idx * KTOT;
#pragma unroll
    for (int it = 0; it < 8; it++) {
        int i2  = tid + it * 256;      // 2048 uint4 = 128 rows x 16
        int row = i2 >> 4;
        int c4  = (i2 & 15) * 4;
        uint4 v = *(const uint4*)&Sh[row * 68 + c4];
        *(uint4*)&Oh[(size_t)(by * 128 + row) * 768 + bx * 128 + c4 * 2] = v;
    }
}

// ---------------------------------------------------------------------------
// Stage 3: split-K contraction, 64x64 output per CTA.
// 576 CTAs x 1024-k slices, 16 chunks of 64, 3-stage cp.async pipeline.
// ---------------------------------------------------------------------------
__global__ void __launch_bounds__(256) contract_kernel()
{
    __shared__ __align__(128) char sm[49152];   // 3 bufs x (A 8KB + B 8KB)
    const int tid = threadIdx.x, lane = tid & 31, wid = tid >> 5;
    const int wm = wid & 3, wn = wid >> 2;
    const int lrow = lane & 15, lseg = lane >> 4;

    uint32_t tBase[3][2];
#pragma unroll
    for (int q = 0; q < 3; q++) {
        tBase[q][0] = smem_u32(sm) + q * 16384;
        tBase[q][1] = tBase[q][0] + 8192;
    }

    auto issue = [&](int ch, int q) {
        const long k0 = (long)blockIdx.x * 1024 + ch * 64;
#pragma unroll
        for (int it = 0; it < 4; it++) {
            int t   = tid + it * 256;   // 0..1023
            int m   = t >> 9;           // 0 = G(A), 1 = W(B)
            int rem = t & 511;
            int row = rem >> 3;         // 0..63
            int kg  = rem & 7;
            const __half* src = (m ? g_Wh : g_Gh) + (size_t)row * KTOT + k0 + kg * 8;
            cpasync16(tBase[q][m] + SW128((uint32_t)(row * 128 + kg * 16)), src);
        }
    };

    float acc[4][4];
#pragma unroll
    for (int j = 0; j < 4; j++)
#pragma unroll
        for (int q = 0; q < 4; q++) acc[j][q] = 0.0f;

    issue(0, 0); CP_COMMIT();
    issue(1, 1); CP_COMMIT();
    for (int ch = 0; ch < 16; ch++) {
        if (ch + 2 < 16) {
            issue(ch + 2, (ch + 2) % 3);
            CP_COMMIT();
            CP_WAIT(2);
        } else if (ch + 1 < 16) {
            CP_WAIT(1);
        } else {
            CP_WAIT(0);
        }
        __syncthreads();
        uint32_t aBase = tBase[ch % 3][0], bBase = tBase[ch % 3][1];
#pragma unroll
        for (int ks = 0; ks < 4; ks++) {
            uint32_t afr[4];
            int arow = wm * 16 + lrow;
            ldsm4(afr, aBase + SW128((uint32_t)(arow * 128 + ks * 32 + lseg * 16)));
#pragma unroll
            for (int nj = 0; nj < 2; nj++) {
                uint32_t bfr[4];
                int brow = wn * 32 + nj * 16 + lrow;
                ldsm4(bfr, bBase + SW128((uint32_t)(brow * 128 + ks * 32 + lseg * 16)));
                mma_fp16(acc[nj * 2],     afr, bfr[0], bfr[2]);
                mma_fp16(acc[nj * 2 + 1], afr, bfr[1], bfr[3]);
            }
        }
        __syncthreads();
    }

    float* outp = g_Zp + (size_t)blockIdx.x * 4096;
#pragma unroll
    for (int nj = 0; nj < 4; nj++) {
        int r = wm * 16 + (lane >> 2);
        int c = wn * 32 + nj * 8 + (lane & 3) * 2;
        *(float2*)&outp[r * 64 + c]       = make_float2(acc[nj][0], acc[nj][1]);
        *(float2*)&outp[(r + 8) * 64 + c] = make_float2(acc[nj][2], acc[nj][3]);
    }
}

// ---------------------------------------------------------------------------
// Stage 3b: deterministic reduce of 576 partials. grid 512 x 256:
// 8 outputs/CTA, 32 threads/output x 18 loads + smem tree.
// ---------------------------------------------------------------------------
__global__ void reduce_z_kernel() {
    __shared__ float sd[256];
    const int il = threadIdx.x & 7, jt = threadIdx.x >> 3;
    const int i = blockIdx.x * 8 + il;
    float s = 0.0f;
#pragma unroll
    for (int u = 0; u < 18; u++)
        s += g_Zp[(size_t)(jt + u * 32) * 4096 + i];
    sd[threadIdx.x] = s;
    __syncthreads();
    for (int off = 16; off; off >>= 1) {
        if (jt < off) sd[threadIdx.x] += sd[threadIdx.x + off * 8];
        __syncthreads();
    }
    if (jt == 0) g_Z[i] = sd[il];
}

// ---------------------------------------------------------------------------
// Stage 4: softmax over n of z/196 + bias
// ---------------------------------------------------------------------------
__global__ void softmax_kernel(const float* __restrict__ bias, float* __restrict__ out) {
    const int b = blockIdx.x, n = threadIdx.x;
    __shared__ float red[64];
    float v = g_Z[b * 64 + n] * (1.0f / 196.0f) + bias[n];
    red[n] = v;
    __syncthreads();
    for (int s = 32; s > 0; s >>= 1) { if (n < s) red[n] = fmaxf(red[n], red[n + s]); __syncthreads(); }
    float m = red[0];
    __syncthreads();
    float e = expf(v - m);
    red[n] = e;
    __syncthreads();
    for (int s = 32; s > 0; s >>= 1) { if (n < s) red[n] += red[n + s]; __syncthreads(); }
    out[b * 64 + n] = e / red[0];
}

// ---------------------------------------------------------------------------
// Launch
// ---------------------------------------------------------------------------
extern "C" void kernel_launch(void* const* d_in, const int* in_sizes, int n_in,
                              void* d_out, int out_size) {
    const float* X    = (const float*)d_in[0];  // [64, 768, 14, 14]
    const float* Y    = (const float*)d_in[1];  // [64, 768, 14, 14]
    const float* w    = (const float*)d_in[2];  // [2, 64, 768, 32]
    const float* bias = (const float*)d_in[3];  // [64]
    float* out = (float*)d_out;                 // [64, 64]

    // Idempotent, not a stream op — safe under graph capture.
    cudaFuncSetAttribute(gemm_unified, cudaFuncAttributeMaxDynamicSharedMemorySize, 98304);

    // Stage 0: fp32 -> fp16 planes
    prep_kernel<<<11520, 256>>>(X, Y, w);

    // Stages 1+2 fused + wave-interleaved: Gram of (X,Y) and of (w0,w1)
    {
        dim3 grid(6, 6, 128);
        gemm_unified<<<grid, 256, 98304>>>();
    }

    // Stage 3: split-K contraction + deterministic reduce
    contract_kernel<<<576, 256>>>();
    reduce_z_kernel<<<512, 256>>>();

    // Stage 4: softmax
    softmax_kernel<<<64, 64>>>(bias, out);
}